// round 1
// baseline (speedup 1.0000x reference)
#include <cuda_runtime.h>
#include <math.h>

// Problem constants (fixed by setup_inputs)
#define Bsz 8
#define Hh  64
#define Ww  128
#define Cc  256
#define DFF 1024
#define TOK (Bsz*Hh*Ww)   // 65536 tokens
#define PIX (Hh*Ww)       // 8192 pixels per image
#define PI_F 3.14159265358979323846f

// -------- scratch (static device globals; no runtime alloc) --------
__device__ float g_xn[(size_t)TOK*Cc];
__device__ float g_y [(size_t)TOK*Cc];
__device__ float g_q [(size_t)TOK*Cc];
__device__ float g_k [(size_t)TOK*Cc];
__device__ float g_v [(size_t)TOK*Cc];
__device__ float g_lepe[(size_t)TOK*Cc];
__device__ float g_ao[(size_t)TOK*Cc];
__device__ float g_x2[(size_t)TOK*Cc];
__device__ float g_h [(size_t)TOK*Cc];
__device__ float g_h1[(size_t)TOK*DFF];
__device__ int   g_map[PIX];

// -------- rotation grid -> nearest-neighbor index map (input-independent) --------
__global__ void map_k() {
    int pix = blockIdx.x * blockDim.x + threadIdx.x;
    if (pix >= PIX) return;
    int h = pix >> 7;        // /128
    int w = pix & 127;
    int wi = h >> 3, p  = h & 7;
    int wj = w >> 3, q0 = w & 7;
    // seq[a] = -1 + 1/ws + (2/ws)*a  (ws=8)
    float seqp = -0.875f + 0.25f * (float)p;
    float seqq = -0.875f + 0.25f * (float)q0;
    float t0 = seqp / 8.0f;    // nH = 8
    float t1 = seqq / 16.0f;   // nW = 16
    float beta = (2.0f * ((float)wi + 0.5f) / 8.0f - 1.0f) * (PI_F * 0.5f);
    float th = t0 * (PI_F * 0.5f) + PI_F * 0.5f;
    float ph = t1 * PI_F;
    float sb = sinf(beta), cb = cosf(beta);
    float st = sinf(th),   ct = cosf(th);
    float sp = sinf(ph),   cp = cosf(ph);
    float arg = -sb * st * cp + cb * ct;
    arg = fminf(1.0f, fmaxf(-1.0f, arg));
    float new_th = acosf(arg);
    float new_ph = atan2f(st * sp, cb * st * cp + sb * ct);
    float lat = (new_th - PI_F * 0.5f) / (PI_F * 0.5f);
    lat = fminf(1.0f, fmaxf(-1.0f, lat));
    float shift = 2.0f * (0.5f - ((float)wj + 0.5f) / 16.0f);
    float lon = new_ph / PI_F - shift;
    if (lon >  1.0f) lon -= 2.0f;
    if (lon < -1.0f) lon += 2.0f;
    // nearest sample, round-half-even (matches jnp.round)
    int iy = (int)rintf(((lat + 1.0f) * (float)Hh - 1.0f) * 0.5f);
    int ix = (int)rintf(((lon + 1.0f) * (float)Ww - 1.0f) * 0.5f);
    g_map[pix] = (iy >= 0 && iy < Hh && ix >= 0 && ix < Ww) ? (iy * Ww + ix) : -1;
}

// -------- layernorm over C=256, one block per token --------
__global__ void ln_k(const float* __restrict__ x, const float* __restrict__ g,
                     const float* __restrict__ b, float* __restrict__ out) {
    const int t = blockIdx.x, c = threadIdx.x;
    size_t base = (size_t)t * Cc;
    float v = x[base + c];
    __shared__ float red[8];
    float s = v;
    #pragma unroll
    for (int o = 16; o > 0; o >>= 1) s += __shfl_xor_sync(0xffffffffu, s, o);
    if ((c & 31) == 0) red[c >> 5] = s;
    __syncthreads();
    float mu = (((red[0]+red[1])+(red[2]+red[3]))+((red[4]+red[5])+(red[6]+red[7]))) * (1.0f/(float)Cc);
    __syncthreads();
    float d = v - mu;
    float s2 = d * d;
    #pragma unroll
    for (int o = 16; o > 0; o >>= 1) s2 += __shfl_xor_sync(0xffffffffu, s2, o);
    if ((c & 31) == 0) red[c >> 5] = s2;
    __syncthreads();
    float var = (((red[0]+red[1])+(red[2]+red[3]))+((red[4]+red[5])+(red[6]+red[7]))) * (1.0f/(float)Cc);
    out[base + c] = d * rsqrtf(var + 1e-5f) * g[c] + b[c];
}

// -------- grid-sample gather: y[b,pix,:] = valid ? xn[b,map[pix],:] : 0 --------
__global__ void sample_k(const float* __restrict__ xn, float* __restrict__ y) {
    int pix = blockIdx.x;
    int c = threadIdx.x;
    int m = g_map[pix];
    #pragma unroll
    for (int b = 0; b < Bsz; b++) {
        float val = 0.0f;
        if (m >= 0) val = xn[((size_t)b * PIX + m) * Cc + c];
        y[((size_t)b * PIX + pix) * Cc + c] = val;
    }
}

// -------- depthwise 3x3 conv (lepe) in [B,H,W,C] layout --------
__global__ void lepe_k(const float* __restrict__ q, const float* __restrict__ rw,
                       const float* __restrict__ rb, float* __restrict__ out) {
    int gid = blockIdx.x;              // b*PIX + pix
    int b   = gid >> 13;
    int pix = gid & (PIX - 1);
    int h = pix >> 7, w = pix & 127;
    int c = threadIdx.x;
    float acc = rb[c];
    #pragma unroll
    for (int ky = 0; ky < 3; ky++) {
        int hh = h + ky - 1;
        if (hh < 0 || hh >= Hh) continue;
        #pragma unroll
        for (int kx = 0; kx < 3; kx++) {
            int ww = w + kx - 1;
            if (ww < 0 || ww >= Ww) continue;
            acc += q[(((size_t)b * Hh + hh) * Ww + ww) * Cc + c] * rw[c * 9 + ky * 3 + kx];
        }
    }
    out[(size_t)gid * Cc + c] = acc;
}

// -------- per-(window,head) attention: 64 tokens x 32 dims --------
__global__ void __launch_bounds__(64) attn_k(
    const float* __restrict__ q, const float* __restrict__ k,
    const float* __restrict__ v, const float* __restrict__ lepe,
    float* __restrict__ out)
{
    const int blk  = blockIdx.x;      // 0..8191
    const int head = blk & 7;
    const int win  = blk >> 3;
    const int b    = win >> 7;
    const int wrem = win & 127;
    const int wi   = wrem >> 4;
    const int wj   = wrem & 15;
    const int tid  = threadIdx.x;     // token within window (0..63)
    const int p    = tid >> 3;
    const int q0   = tid & 7;
    const int t    = ((b * Hh + wi * 8 + p) * Ww + wj * 8 + q0);
    const int cbase = head * 32;
    const float scale = 0.17677669529663687f;  // 1/sqrt(32)

    __shared__ float ks[64][36];
    __shared__ float vs[64][36];
    float qreg[32];
    size_t ioff = (size_t)t * Cc + cbase;
    #pragma unroll
    for (int d = 0; d < 32; d += 4) {
        float4 qq = *(const float4*)(q + ioff + d);
        qreg[d] = qq.x * scale; qreg[d+1] = qq.y * scale;
        qreg[d+2] = qq.z * scale; qreg[d+3] = qq.w * scale;
        *(float4*)&ks[tid][d] = *(const float4*)(k + ioff + d);
        *(float4*)&vs[tid][d] = *(const float4*)(v + ioff + d);
    }
    __syncthreads();

    float s[64];
    float mx = -1e30f;
    #pragma unroll
    for (int j = 0; j < 64; j++) {
        float dot = 0.0f;
        #pragma unroll
        for (int d = 0; d < 32; d += 4) {
            float4 kk = *(const float4*)&ks[j][d];
            dot += qreg[d] * kk.x + qreg[d+1] * kk.y + qreg[d+2] * kk.z + qreg[d+3] * kk.w;
        }
        s[j] = dot;
        mx = fmaxf(mx, dot);
    }
    float sum = 0.0f;
    #pragma unroll
    for (int j = 0; j < 64; j++) { float e = expf(s[j] - mx); s[j] = e; sum += e; }
    float inv = 1.0f / sum;

    float o[32];
    #pragma unroll
    for (int d = 0; d < 32; d++) o[d] = 0.0f;
    #pragma unroll
    for (int j = 0; j < 64; j++) {
        float wgt = s[j] * inv;
        #pragma unroll
        for (int d = 0; d < 32; d += 4) {
            float4 vv = *(const float4*)&vs[j][d];
            o[d] += wgt * vv.x; o[d+1] += wgt * vv.y;
            o[d+2] += wgt * vv.z; o[d+3] += wgt * vv.w;
        }
    }
    #pragma unroll
    for (int d = 0; d < 32; d += 4) {
        float4 lp = *(const float4*)(lepe + ioff + d);
        float4 r;
        r.x = o[d] + lp.x; r.y = o[d+1] + lp.y;
        r.z = o[d+2] + lp.z; r.w = o[d+3] + lp.w;
        *(float4*)(out + ioff + d) = r;
    }
}

// -------- SGEMM: C[M,N] = A[M,K] @ B[K,N] + bias (+epilogue) --------
// 128x128 tile, BK=8, 256 threads, 8x8 microtile.
// MODE 0: +bias   MODE 1: gelu(+bias)   MODE 2: +bias +res
template<int MODE>
__global__ void __launch_bounds__(256) sgemm_k(
    const float* __restrict__ A, const float* __restrict__ B,
    const float* __restrict__ bias, const float* __restrict__ res,
    float* __restrict__ C, int M, int N, int K)
{
    __shared__ float As[8][132];   // padded: conflict-free transposed stores
    __shared__ float Bs[8][128];
    const int tid = threadIdx.x;
    const int bm = blockIdx.y * 128;
    const int bn = blockIdx.x * 128;
    const int tx = tid & 15, ty = tid >> 4;
    const int ar = tid >> 1, ak = (tid & 1) << 2;
    const int bk = tid >> 5, bn4 = (tid & 31) << 2;
    const float* Ap = A + (size_t)(bm + ar) * K + ak;
    const float* Bp = B + (size_t)bk * N + bn + bn4;

    float acc[8][8];
    #pragma unroll
    for (int i = 0; i < 8; i++)
        #pragma unroll
        for (int j = 0; j < 8; j++) acc[i][j] = 0.0f;

    for (int k0 = 0; k0 < K; k0 += 8) {
        float4 a4 = *(const float4*)(Ap + k0);
        float4 b4 = *(const float4*)(Bp + (size_t)k0 * N);
        As[ak+0][ar] = a4.x; As[ak+1][ar] = a4.y;
        As[ak+2][ar] = a4.z; As[ak+3][ar] = a4.w;
        *(float4*)&Bs[bk][bn4] = b4;
        __syncthreads();
        #pragma unroll
        for (int kk = 0; kk < 8; kk++) {
            float4 a0 = *(const float4*)&As[kk][ty * 8];
            float4 a1 = *(const float4*)&As[kk][ty * 8 + 4];
            float4 b0 = *(const float4*)&Bs[kk][tx * 8];
            float4 b1 = *(const float4*)&Bs[kk][tx * 8 + 4];
            float af[8] = {a0.x, a0.y, a0.z, a0.w, a1.x, a1.y, a1.z, a1.w};
            float bf[8] = {b0.x, b0.y, b0.z, b0.w, b1.x, b1.y, b1.z, b1.w};
            #pragma unroll
            for (int i = 0; i < 8; i++)
                #pragma unroll
                for (int j = 0; j < 8; j++)
                    acc[i][j] += af[i] * bf[j];
        }
        __syncthreads();
    }

    const int row0 = bm + ty * 8;
    const int col0 = bn + tx * 8;
    #pragma unroll
    for (int i = 0; i < 8; i++) {
        size_t off = (size_t)(row0 + i) * N + col0;
        #pragma unroll
        for (int j = 0; j < 8; j++) {
            float vv = acc[i][j] + bias[col0 + j];
            if (MODE == 1) vv = 0.5f * vv * (1.0f + erff(vv * 0.70710678118654752440f));
            if (MODE == 2) vv += res[off + j];
            C[off + j] = vv;
        }
    }
}

extern "C" void kernel_launch(void* const* d_in, const int* in_sizes, int n_in,
                              void* d_out, int out_size) {
    const float* x   = (const float*)d_in[0];
    // d_in[1]=H, d_in[2]=W (int32, fixed 64/128 — hardcoded)
    const float* n1g = (const float*)d_in[3];
    const float* n1b = (const float*)d_in[4];
    const float* wq  = (const float*)d_in[5];
    const float* bq  = (const float*)d_in[6];
    const float* wk  = (const float*)d_in[7];
    const float* bk_ = (const float*)d_in[8];
    const float* wv  = (const float*)d_in[9];
    const float* bv  = (const float*)d_in[10];
    const float* rw  = (const float*)d_in[11];
    const float* rb  = (const float*)d_in[12];
    const float* pw  = (const float*)d_in[13];
    const float* pb  = (const float*)d_in[14];
    const float* n2g = (const float*)d_in[15];
    const float* n2b = (const float*)d_in[16];
    const float* f1w = (const float*)d_in[17];
    const float* f1b = (const float*)d_in[18];
    const float* f2w = (const float*)d_in[19];
    const float* f2b = (const float*)d_in[20];
    float* out = (float*)d_out;

    float *p_xn, *p_y, *p_q, *p_k, *p_v, *p_lepe, *p_ao, *p_x2, *p_h, *p_h1;
    cudaGetSymbolAddress((void**)&p_xn,   g_xn);
    cudaGetSymbolAddress((void**)&p_y,    g_y);
    cudaGetSymbolAddress((void**)&p_q,    g_q);
    cudaGetSymbolAddress((void**)&p_k,    g_k);
    cudaGetSymbolAddress((void**)&p_v,    g_v);
    cudaGetSymbolAddress((void**)&p_lepe, g_lepe);
    cudaGetSymbolAddress((void**)&p_ao,   g_ao);
    cudaGetSymbolAddress((void**)&p_x2,   g_x2);
    cudaGetSymbolAddress((void**)&p_h,    g_h);
    cudaGetSymbolAddress((void**)&p_h1,   g_h1);

    map_k<<<PIX / 256, 256>>>();
    ln_k<<<TOK, 256>>>(x, n1g, n1b, p_xn);
    sample_k<<<PIX, 256>>>(p_xn, p_y);

    dim3 gC(Cc / 128, TOK / 128);     // (2, 512)
    sgemm_k<0><<<gC, 256>>>(p_xn, wq, bq,  nullptr, p_q, TOK, Cc, Cc);
    sgemm_k<0><<<gC, 256>>>(p_y,  wk, bk_, nullptr, p_k, TOK, Cc, Cc);
    sgemm_k<0><<<gC, 256>>>(p_xn, wv, bv,  nullptr, p_v, TOK, Cc, Cc);

    lepe_k<<<TOK, 256>>>(p_q, rw, rb, p_lepe);
    attn_k<<<8192, 64>>>(p_q, p_k, p_v, p_lepe, p_ao);

    sgemm_k<2><<<gC, 256>>>(p_ao, pw, pb, x, p_x2, TOK, Cc, Cc);

    ln_k<<<TOK, 256>>>(p_x2, n2g, n2b, p_h);

    dim3 gF(DFF / 128, TOK / 128);    // (8, 512)
    sgemm_k<1><<<gF, 256>>>(p_h,  f1w, f1b, nullptr, p_h1, TOK, DFF, Cc);
    sgemm_k<2><<<gC, 256>>>(p_h1, f2w, f2b, p_x2,    out,  TOK, Cc, DFF);
}

// round 3
// speedup vs baseline: 1.3810x; 1.3810x over previous
#include <cuda_runtime.h>
#include <math.h>
#include <stdint.h>

// Problem constants (fixed by setup_inputs)
#define Bsz 8
#define Hh  64
#define Ww  128
#define Cc  256
#define DFF 1024
#define TOK (Bsz*Hh*Ww)   // 65536 tokens
#define PIX (Hh*Ww)       // 8192 pixels per image
#define PI_F 3.14159265358979323846f

// -------- scratch (static device globals; no runtime alloc) --------
__device__ float g_xn[(size_t)TOK*Cc];
__device__ float g_y [(size_t)TOK*Cc];
__device__ float g_q [(size_t)TOK*Cc];
__device__ float g_k [(size_t)TOK*Cc];
__device__ float g_v [(size_t)TOK*Cc];
__device__ float g_lepe[(size_t)TOK*Cc];
__device__ float g_ao[(size_t)TOK*Cc];
__device__ float g_x2[(size_t)TOK*Cc];
__device__ float g_h [(size_t)TOK*Cc];
__device__ float g_h1[(size_t)TOK*DFF];
__device__ int   g_map[PIX];
// transposed weights: wqT wkT wvT pwT (64K floats each) + f1T (256K) + f2T (256K)
__device__ float g_bt[4*65536 + 2*262144];

__device__ __forceinline__ uint32_t f2tf32(float x) {
    uint32_t r;
    asm("cvt.rna.tf32.f32 %0, %1;" : "=r"(r) : "f"(x));
    return r;
}
__device__ __forceinline__ void mma_tf32(float* c, const uint32_t* a, const uint32_t* b) {
    asm volatile(
        "mma.sync.aligned.m16n8k8.row.col.f32.tf32.tf32.f32 "
        "{%0,%1,%2,%3}, {%4,%5,%6,%7}, {%8,%9}, {%0,%1,%2,%3};"
        : "+f"(c[0]), "+f"(c[1]), "+f"(c[2]), "+f"(c[3])
        : "r"(a[0]), "r"(a[1]), "r"(a[2]), "r"(a[3]), "r"(b[0]), "r"(b[1]));
}

// ======== tf32 mma.sync GEMM: C[M,N] = A[M,K] @ Bt[N,K]^T + bias (+epilogue) ========
// BM=128, BN=128, BK=32; 256 threads = 8 warps (2m x 4n); warp tile 64x32.
// Smem in mma-fragment-permuted layout:
//   A float4 unit index ua = ((kb*8 + mb)*32 + lane) ^ kb   (mb 0..7, kb 0..3)
//   B float2 unit index ub = ((kb*16 + nb)*32 + lane) ^ kb  (nb 0..15)
// MODE 0: +bias   MODE 1: gelu(+bias)   MODE 2: +bias +res
#define GSM_BUF 32768          // bytes per stage (A 16KB + B 16KB)
#define GSM_TOT (2*GSM_BUF)
template<int MODE>
__global__ void __launch_bounds__(256, 1) mmagemm_k(
    const float* __restrict__ A, const float* __restrict__ Bt,
    const float* __restrict__ bias, const float* __restrict__ res,
    float* __restrict__ C, int N, int K)
{
    extern __shared__ char smem[];
    const int tid  = threadIdx.x;
    const int wid  = tid >> 5, lane = tid & 31;
    const int gid  = lane >> 2, tg = lane & 3;
    const int wm   = wid >> 2, wn = wid & 3;      // warp grid 2x4
    const int bm = blockIdx.y * 128;
    const int bn = blockIdx.x * 128;
    const int NC = K >> 5;

    const int frow = tid >> 3, ffc = tid & 7;     // per-thread gmem float4 slot

    float acc[4][4][4];
    #pragma unroll
    for (int mi = 0; mi < 4; mi++)
        #pragma unroll
        for (int ni = 0; ni < 4; ni++)
            #pragma unroll
            for (int r = 0; r < 4; r++) acc[mi][ni][r] = 0.0f;

    float4 a4[4], b4[4];

    // prologue: load + stage chunk 0
    #pragma unroll
    for (int i = 0; i < 4; i++) {
        int row = frow + i * 32;
        a4[i] = *(const float4*)(A  + (size_t)(bm + row) * K + ffc * 4);
        b4[i] = *(const float4*)(Bt + (size_t)(bn + row) * K + ffc * 4);
    }
    {
        float* As = (float*)smem;
        float* Bs = As + 4096;
        const int kb = ffc >> 1, i2 = ffc & 1;
        #pragma unroll
        for (int i = 0; i < 4; i++) {
            int row = frow + i * 32;
            int mb = row >> 4, rr = row & 15, ga = rr & 7, i1 = rr >> 3;
            int nb = row >> 3, gb = row & 7;
            float va[4] = {a4[i].x, a4[i].y, a4[i].z, a4[i].w};
            float vb[4] = {b4[i].x, b4[i].y, b4[i].z, b4[i].w};
            #pragma unroll
            for (int e = 0; e < 4; e++) {
                uint32_t ua = (uint32_t)(((kb * 8 + mb) * 32 + ga * 4 + e) ^ kb);
                As[ua * 4 + i1 + 2 * i2] = __uint_as_float(f2tf32(va[e]));
                uint32_t ub = (uint32_t)(((kb * 16 + nb) * 32 + gb * 4 + e) ^ kb);
                Bs[ub * 2 + i2] = __uint_as_float(f2tf32(vb[e]));
            }
        }
    }
    __syncthreads();

    for (int c = 0; c < NC; c++) {
        const int k0n = (c + 1) << 5;
        if (c + 1 < NC) {
            #pragma unroll
            for (int i = 0; i < 4; i++) {
                int row = frow + i * 32;
                a4[i] = *(const float4*)(A  + (size_t)(bm + row) * K + k0n + ffc * 4);
                b4[i] = *(const float4*)(Bt + (size_t)(bn + row) * K + k0n + ffc * 4);
            }
        }

        const float* As = (const float*)(smem + (c & 1) * GSM_BUF);
        const float* Bs = As + 4096;
        #pragma unroll
        for (int kb = 0; kb < 4; kb++) {
            uint32_t af[4][4];
            uint32_t bf[4][2];
            #pragma unroll
            for (int mi = 0; mi < 4; mi++) {
                uint32_t ua = (uint32_t)(((kb * 8 + wm * 4 + mi) * 32 + lane) ^ kb);
                uint4 t = *(const uint4*)(As + ua * 4);
                af[mi][0] = t.x; af[mi][1] = t.y; af[mi][2] = t.z; af[mi][3] = t.w;
            }
            #pragma unroll
            for (int ni = 0; ni < 4; ni++) {
                uint32_t ub = (uint32_t)(((kb * 16 + wn * 4 + ni) * 32 + lane) ^ kb);
                uint2 t = *(const uint2*)(Bs + ub * 2);
                bf[ni][0] = t.x; bf[ni][1] = t.y;
            }
            #pragma unroll
            for (int mi = 0; mi < 4; mi++)
                #pragma unroll
                for (int ni = 0; ni < 4; ni++)
                    mma_tf32(acc[mi][ni], af[mi], bf[ni]);
        }

        if (c + 1 < NC) {
            float* Asw = (float*)(smem + ((c + 1) & 1) * GSM_BUF);
            float* Bsw = Asw + 4096;
            const int kb = ffc >> 1, i2 = ffc & 1;
            #pragma unroll
            for (int i = 0; i < 4; i++) {
                int row = frow + i * 32;
                int mb = row >> 4, rr = row & 15, ga = rr & 7, i1 = rr >> 3;
                int nb = row >> 3, gb = row & 7;
                float va[4] = {a4[i].x, a4[i].y, a4[i].z, a4[i].w};
                float vb[4] = {b4[i].x, b4[i].y, b4[i].z, b4[i].w};
                #pragma unroll
                for (int e = 0; e < 4; e++) {
                    uint32_t ua = (uint32_t)(((kb * 8 + mb) * 32 + ga * 4 + e) ^ kb);
                    Asw[ua * 4 + i1 + 2 * i2] = __uint_as_float(f2tf32(va[e]));
                    uint32_t ub = (uint32_t)(((kb * 16 + nb) * 32 + gb * 4 + e) ^ kb);
                    Bsw[ub * 2 + i2] = __uint_as_float(f2tf32(vb[e]));
                }
            }
            __syncthreads();
        }
    }

    // ---- epilogue ----
    #pragma unroll
    for (int mi = 0; mi < 4; mi++) {
        const int r0 = bm + wm * 64 + mi * 16 + gid;
        #pragma unroll
        for (int ni = 0; ni < 4; ni++) {
            const int col = bn + wn * 32 + ni * 8 + tg * 2;
            float bx = bias[col], by = bias[col + 1];
            #pragma unroll
            for (int hh = 0; hh < 2; hh++) {
                const int row = r0 + hh * 8;
                float ox = acc[mi][ni][hh * 2]     + bx;
                float oy = acc[mi][ni][hh * 2 + 1] + by;
                size_t off = (size_t)row * N + col;
                if (MODE == 1) {
                    ox = 0.5f * ox * (1.0f + erff(ox * 0.70710678118654752440f));
                    oy = 0.5f * oy * (1.0f + erff(oy * 0.70710678118654752440f));
                }
                if (MODE == 2) {
                    float2 rv = *(const float2*)(res + off);
                    ox += rv.x; oy += rv.y;
                }
                float2 o = {ox, oy};
                *(float2*)(C + off) = o;
            }
        }
    }
}

// -------- transpose: out[c*R + r] = in[r*C + c] --------
__global__ void transpose_k(const float* __restrict__ in, float* __restrict__ out,
                            int R, int Ccols) {
    __shared__ float t[32][33];
    int bx = blockIdx.x * 32, by = blockIdx.y * 32;
    int x = bx + threadIdx.x;
    #pragma unroll
    for (int i = 0; i < 32; i += 8)
        t[threadIdx.y + i][threadIdx.x] = in[(size_t)(by + threadIdx.y + i) * Ccols + x];
    __syncthreads();
    int x2 = by + threadIdx.x;
    #pragma unroll
    for (int i = 0; i < 32; i += 8)
        out[(size_t)(bx + threadIdx.y + i) * R + x2] = t[threadIdx.x][threadIdx.y + i];
}

// -------- rotation grid -> nearest-neighbor index map (input-independent) --------
__global__ void map_k() {
    int pix = blockIdx.x * blockDim.x + threadIdx.x;
    if (pix >= PIX) return;
    int h = pix >> 7;
    int w = pix & 127;
    int wi = h >> 3, p  = h & 7;
    int wj = w >> 3, q0 = w & 7;
    float seqp = -0.875f + 0.25f * (float)p;
    float seqq = -0.875f + 0.25f * (float)q0;
    float t0 = seqp / 8.0f;
    float t1 = seqq / 16.0f;
    float beta = (2.0f * ((float)wi + 0.5f) / 8.0f - 1.0f) * (PI_F * 0.5f);
    float th = t0 * (PI_F * 0.5f) + PI_F * 0.5f;
    float ph = t1 * PI_F;
    float sb = sinf(beta), cb = cosf(beta);
    float st = sinf(th),   ct = cosf(th);
    float sp = sinf(ph),   cp = cosf(ph);
    float arg = -sb * st * cp + cb * ct;
    arg = fminf(1.0f, fmaxf(-1.0f, arg));
    float new_th = acosf(arg);
    float new_ph = atan2f(st * sp, cb * st * cp + sb * ct);
    float lat = (new_th - PI_F * 0.5f) / (PI_F * 0.5f);
    lat = fminf(1.0f, fmaxf(-1.0f, lat));
    float shift = 2.0f * (0.5f - ((float)wj + 0.5f) / 16.0f);
    float lon = new_ph / PI_F - shift;
    if (lon >  1.0f) lon -= 2.0f;
    if (lon < -1.0f) lon += 2.0f;
    int iy = (int)rintf(((lat + 1.0f) * (float)Hh - 1.0f) * 0.5f);
    int ix = (int)rintf(((lon + 1.0f) * (float)Ww - 1.0f) * 0.5f);
    g_map[pix] = (iy >= 0 && iy < Hh && ix >= 0 && ix < Ww) ? (iy * Ww + ix) : -1;
}

// -------- layernorm over C=256, one block per token --------
__global__ void ln_k(const float* __restrict__ x, const float* __restrict__ g,
                     const float* __restrict__ b, float* __restrict__ out) {
    const int t = blockIdx.x, c = threadIdx.x;
    size_t base = (size_t)t * Cc;
    float v = x[base + c];
    __shared__ float red[8];
    float s = v;
    #pragma unroll
    for (int o = 16; o > 0; o >>= 1) s += __shfl_xor_sync(0xffffffffu, s, o);
    if ((c & 31) == 0) red[c >> 5] = s;
    __syncthreads();
    float mu = (((red[0]+red[1])+(red[2]+red[3]))+((red[4]+red[5])+(red[6]+red[7]))) * (1.0f/(float)Cc);
    __syncthreads();
    float d = v - mu;
    float s2 = d * d;
    #pragma unroll
    for (int o = 16; o > 0; o >>= 1) s2 += __shfl_xor_sync(0xffffffffu, s2, o);
    if ((c & 31) == 0) red[c >> 5] = s2;
    __syncthreads();
    float var = (((red[0]+red[1])+(red[2]+red[3]))+((red[4]+red[5])+(red[6]+red[7]))) * (1.0f/(float)Cc);
    out[base + c] = d * rsqrtf(var + 1e-5f) * g[c] + b[c];
}

// -------- grid-sample gather --------
__global__ void sample_k(const float* __restrict__ xn, float* __restrict__ y) {
    int pix = blockIdx.x;
    int c = threadIdx.x;
    int m = g_map[pix];
    #pragma unroll
    for (int b = 0; b < Bsz; b++) {
        float val = 0.0f;
        if (m >= 0) val = xn[((size_t)b * PIX + m) * Cc + c];
        y[((size_t)b * PIX + pix) * Cc + c] = val;
    }
}

// -------- depthwise 3x3 conv (lepe) --------
__global__ void lepe_k(const float* __restrict__ q, const float* __restrict__ rw,
                       const float* __restrict__ rb, float* __restrict__ out) {
    int gid = blockIdx.x;
    int b   = gid >> 13;
    int pix = gid & (PIX - 1);
    int h = pix >> 7, w = pix & 127;
    int c = threadIdx.x;
    float acc = rb[c];
    #pragma unroll
    for (int ky = 0; ky < 3; ky++) {
        int hh = h + ky - 1;
        if (hh < 0 || hh >= Hh) continue;
        #pragma unroll
        for (int kx = 0; kx < 3; kx++) {
            int ww = w + kx - 1;
            if (ww < 0 || ww >= Ww) continue;
            acc += q[(((size_t)b * Hh + hh) * Ww + ww) * Cc + c] * rw[c * 9 + ky * 3 + kx];
        }
    }
    out[(size_t)gid * Cc + c] = acc;
}

// -------- per-(window,head) attention --------
__global__ void __launch_bounds__(64) attn_k(
    const float* __restrict__ q, const float* __restrict__ k,
    const float* __restrict__ v, const float* __restrict__ lepe,
    float* __restrict__ out)
{
    const int blk  = blockIdx.x;
    const int head = blk & 7;
    const int win  = blk >> 3;
    const int b    = win >> 7;
    const int wrem = win & 127;
    const int wi   = wrem >> 4;
    const int wj   = wrem & 15;
    const int tid  = threadIdx.x;
    const int p    = tid >> 3;
    const int q0   = tid & 7;
    const int t    = ((b * Hh + wi * 8 + p) * Ww + wj * 8 + q0);
    const int cbase = head * 32;
    const float scale = 0.17677669529663687f;

    __shared__ float ks[64][36];
    __shared__ float vs[64][36];
    float qreg[32];
    size_t ioff = (size_t)t * Cc + cbase;
    #pragma unroll
    for (int d = 0; d < 32; d += 4) {
        float4 qq = *(const float4*)(q + ioff + d);
        qreg[d] = qq.x * scale; qreg[d+1] = qq.y * scale;
        qreg[d+2] = qq.z * scale; qreg[d+3] = qq.w * scale;
        *(float4*)&ks[tid][d] = *(const float4*)(k + ioff + d);
        *(float4*)&vs[tid][d] = *(const float4*)(v + ioff + d);
    }
    __syncthreads();

    float s[64];
    float mx = -1e30f;
    #pragma unroll
    for (int j = 0; j < 64; j++) {
        float dot = 0.0f;
        #pragma unroll
        for (int d = 0; d < 32; d += 4) {
            float4 kk = *(const float4*)&ks[j][d];
            dot += qreg[d] * kk.x + qreg[d+1] * kk.y + qreg[d+2] * kk.z + qreg[d+3] * kk.w;
        }
        s[j] = dot;
        mx = fmaxf(mx, dot);
    }
    float sum = 0.0f;
    #pragma unroll
    for (int j = 0; j < 64; j++) { float e = expf(s[j] - mx); s[j] = e; sum += e; }
    float inv = 1.0f / sum;

    float o[32];
    #pragma unroll
    for (int d = 0; d < 32; d++) o[d] = 0.0f;
    #pragma unroll
    for (int j = 0; j < 64; j++) {
        float wgt = s[j] * inv;
        #pragma unroll
        for (int d = 0; d < 32; d += 4) {
            float4 vv = *(const float4*)&vs[j][d];
            o[d] += wgt * vv.x; o[d+1] += wgt * vv.y;
            o[d+2] += wgt * vv.z; o[d+3] += wgt * vv.w;
        }
    }
    #pragma unroll
    for (int d = 0; d < 32; d += 4) {
        float4 lp = *(const float4*)(lepe + ioff + d);
        float4 r;
        r.x = o[d] + lp.x; r.y = o[d+1] + lp.y;
        r.z = o[d+2] + lp.z; r.w = o[d+3] + lp.w;
        *(float4*)(out + ioff + d) = r;
    }
}

extern "C" void kernel_launch(void* const* d_in, const int* in_sizes, int n_in,
                              void* d_out, int out_size) {
    const float* x   = (const float*)d_in[0];
    const float* n1g = (const float*)d_in[3];
    const float* n1b = (const float*)d_in[4];
    const float* wq  = (const float*)d_in[5];
    const float* bq  = (const float*)d_in[6];
    const float* wk  = (const float*)d_in[7];
    const float* bk_ = (const float*)d_in[8];
    const float* wv  = (const float*)d_in[9];
    const float* bv  = (const float*)d_in[10];
    const float* rw  = (const float*)d_in[11];
    const float* rb  = (const float*)d_in[12];
    const float* pw  = (const float*)d_in[13];
    const float* pb  = (const float*)d_in[14];
    const float* n2g = (const float*)d_in[15];
    const float* n2b = (const float*)d_in[16];
    const float* f1w = (const float*)d_in[17];
    const float* f1b = (const float*)d_in[18];
    const float* f2w = (const float*)d_in[19];
    const float* f2b = (const float*)d_in[20];
    float* out = (float*)d_out;

    float *p_xn, *p_y, *p_q, *p_k, *p_v, *p_lepe, *p_ao, *p_x2, *p_h, *p_h1, *p_bt;
    cudaGetSymbolAddress((void**)&p_xn,   g_xn);
    cudaGetSymbolAddress((void**)&p_y,    g_y);
    cudaGetSymbolAddress((void**)&p_q,    g_q);
    cudaGetSymbolAddress((void**)&p_k,    g_k);
    cudaGetSymbolAddress((void**)&p_v,    g_v);
    cudaGetSymbolAddress((void**)&p_lepe, g_lepe);
    cudaGetSymbolAddress((void**)&p_ao,   g_ao);
    cudaGetSymbolAddress((void**)&p_x2,   g_x2);
    cudaGetSymbolAddress((void**)&p_h,    g_h);
    cudaGetSymbolAddress((void**)&p_h1,   g_h1);
    cudaGetSymbolAddress((void**)&p_bt,   g_bt);

    float* wqT = p_bt;
    float* wkT = p_bt + 65536;
    float* wvT = p_bt + 2*65536;
    float* pwT = p_bt + 3*65536;
    float* f1T = p_bt + 4*65536;            // [1024][256]
    float* f2T = p_bt + 4*65536 + 262144;   // [256][1024]

    cudaFuncSetAttribute(mmagemm_k<0>, cudaFuncAttributeMaxDynamicSharedMemorySize, GSM_TOT);
    cudaFuncSetAttribute(mmagemm_k<1>, cudaFuncAttributeMaxDynamicSharedMemorySize, GSM_TOT);
    cudaFuncSetAttribute(mmagemm_k<2>, cudaFuncAttributeMaxDynamicSharedMemorySize, GSM_TOT);

    dim3 trb(32, 8);
    transpose_k<<<dim3(8, 8),  trb>>>(wq,  wqT, 256, 256);
    transpose_k<<<dim3(8, 8),  trb>>>(wk,  wkT, 256, 256);
    transpose_k<<<dim3(8, 8),  trb>>>(wv,  wvT, 256, 256);
    transpose_k<<<dim3(8, 8),  trb>>>(pw,  pwT, 256, 256);
    transpose_k<<<dim3(32, 8), trb>>>(f1w, f1T, 256, 1024);
    transpose_k<<<dim3(8, 32), trb>>>(f2w, f2T, 1024, 256);

    map_k<<<PIX / 256, 256>>>();
    ln_k<<<TOK, 256>>>(x, n1g, n1b, p_xn);
    sample_k<<<PIX, 256>>>(p_xn, p_y);

    dim3 gC(Cc / 128, TOK / 128);      // (2, 512)
    mmagemm_k<0><<<gC, 256, GSM_TOT>>>(p_xn, wqT, bq,  nullptr, p_q, Cc, Cc);
    mmagemm_k<0><<<gC, 256, GSM_TOT>>>(p_y,  wkT, bk_, nullptr, p_k, Cc, Cc);
    mmagemm_k<0><<<gC, 256, GSM_TOT>>>(p_xn, wvT, bv,  nullptr, p_v, Cc, Cc);

    lepe_k<<<TOK, 256>>>(p_q, rw, rb, p_lepe);
    attn_k<<<8192, 64>>>(p_q, p_k, p_v, p_lepe, p_ao);

    mmagemm_k<2><<<gC, 256, GSM_TOT>>>(p_ao, pwT, pb, x, p_x2, Cc, Cc);

    ln_k<<<TOK, 256>>>(p_x2, n2g, n2b, p_h);

    dim3 gF(DFF / 128, TOK / 128);     // (8, 512)
    mmagemm_k<1><<<gF, 256, GSM_TOT>>>(p_h,  f1T, f1b, nullptr, p_h1, DFF, Cc);
    mmagemm_k<2><<<gC, 256, GSM_TOT>>>(p_h1, f2T, f2b, p_x2,    out,  Cc, DFF);
}

// round 4
// speedup vs baseline: 2.1758x; 1.5756x over previous
#include <cuda_runtime.h>
#include <math.h>
#include <stdint.h>

// Problem constants (fixed by setup_inputs)
#define Bsz 8
#define Hh  64
#define Ww  128
#define Cc  256
#define DFF 1024
#define TOK (Bsz*Hh*Ww)   // 65536 tokens
#define PIX (Hh*Ww)       // 8192 pixels per image
#define PI_F 3.14159265358979323846f

// -------- scratch (static device globals; no runtime alloc) --------
__device__ float g_xn[(size_t)TOK*Cc];
__device__ float g_y [(size_t)TOK*Cc];
__device__ float g_q [(size_t)TOK*Cc];
__device__ float g_k [(size_t)TOK*Cc];
__device__ float g_v [(size_t)TOK*Cc];
__device__ float g_lepe[(size_t)TOK*Cc];
__device__ float g_ao[(size_t)TOK*Cc];
__device__ float g_x2[(size_t)TOK*Cc];
__device__ float g_h [(size_t)TOK*Cc];
__device__ float g_h1[(size_t)TOK*DFF];
__device__ int   g_map[PIX];
// transposed weights: wqT wkT wvT pwT (64K floats each) + f1T (256K) + f2T (256K)
__device__ float g_bt[4*65536 + 2*262144];

__device__ __forceinline__ uint32_t packbf(float lo, float hi) {
    uint32_t r;
    asm("cvt.rn.bf16x2.f32 %0, %1, %2;" : "=r"(r) : "f"(hi), "f"(lo));
    return r;
}
__device__ __forceinline__ void mma_bf16(float* c, const uint32_t* a, const uint32_t* b) {
    asm volatile(
        "mma.sync.aligned.m16n8k16.row.col.f32.bf16.bf16.f32 "
        "{%0,%1,%2,%3}, {%4,%5,%6,%7}, {%8,%9}, {%0,%1,%2,%3};"
        : "+f"(c[0]), "+f"(c[1]), "+f"(c[2]), "+f"(c[3])
        : "r"(a[0]), "r"(a[1]), "r"(a[2]), "r"(a[3]), "r"(b[0]), "r"(b[1]));
}

// ======== bf16 mma.sync GEMM: C[M,N] = A[M,K] @ Bt[N,K]^T + bias (+epilogue) ========
// BM=128, BN=128, BK=32; 512 threads = 16 warps (4m x 4n); warp tile 32x32.
// Smem holds bf16x2 units (uint32) in mma-fragment order:
//   A: unit = ((kb*8 + mb)*32 + lane)*4 + r   (mb 0..7 = 16-row frag, kb 0..1, r=a-reg 0..3)
//   B: unit = ((kb*16 + nb)*32 + lane)*2 + r  (nb 0..15 = 8-col frag, r=b-reg 0..1)
// MODE 0: +bias   MODE 1: gelu(+bias)   MODE 2: +bias +res
template<int MODE>
__global__ void __launch_bounds__(512) bfgemm_k(
    const float* __restrict__ A, const float* __restrict__ Bt,
    const float* __restrict__ bias, const float* __restrict__ res,
    float* __restrict__ C, int N, int K)
{
    __shared__ uint32_t sm[2][4096];   // per buf: As [0,2048) | Bs [2048,4096)  (32KB total)
    const int tid = threadIdx.x;
    const int wid = tid >> 5, lane = tid & 31;
    const int g = lane >> 2, tg = lane & 3;
    const int wm = wid >> 2, wn = wid & 3;     // warp grid 4x4
    const int bm = blockIdx.y * 128;
    const int bn = blockIdx.x * 128;
    const int NC = K >> 5;

    float acc[2][4][4];
    #pragma unroll
    for (int mi = 0; mi < 2; mi++)
        #pragma unroll
        for (int ni = 0; ni < 4; ni++)
            #pragma unroll
            for (int r = 0; r < 4; r++) acc[mi][ni][r] = 0.0f;

    float4 a4[2], b4[2];

    auto ldg = [&](int c) {
        const int k0 = c << 5;
        #pragma unroll
        for (int i = 0; i < 2; i++) {
            int s = tid + i * 512;
            int row = s >> 3, f = s & 7;
            a4[i] = *(const float4*)(A  + (size_t)(bm + row) * K + k0 + f * 4);
            b4[i] = *(const float4*)(Bt + (size_t)(bn + row) * K + k0 + f * 4);
        }
    };
    auto sts = [&](int buf) {
        uint32_t* As = sm[buf];
        uint32_t* Bs = sm[buf] + 2048;
        #pragma unroll
        for (int i = 0; i < 2; i++) {
            int s = tid + i * 512;
            int row = s >> 3, f = s & 7;
            int kb = f >> 2, rem = f & 3;
            int i2 = rem >> 1, tg0 = (rem & 1) * 2;
            // A: mb/ga/i1 from row
            int mb = row >> 4, gr = row & 15, ga = gr & 7, i1 = gr >> 3;
            uint32_t ab = (uint32_t)(((kb * 8 + mb) * 32 + ga * 4 + tg0) * 4 + i1 + 2 * i2);
            As[ab]     = packbf(a4[i].x, a4[i].y);
            As[ab + 4] = packbf(a4[i].z, a4[i].w);
            // B: nb/gb from row (= n index)
            int nb = row >> 3, gb = row & 7;
            uint32_t bb = (uint32_t)(((kb * 16 + nb) * 32 + gb * 4 + tg0) * 2 + i2);
            Bs[bb]     = packbf(b4[i].x, b4[i].y);
            Bs[bb + 2] = packbf(b4[i].z, b4[i].w);
        }
    };

    ldg(0);
    sts(0);
    __syncthreads();

    for (int c = 0; c < NC; c++) {
        if (c + 1 < NC) ldg(c + 1);
        const uint32_t* As = sm[c & 1];
        const uint32_t* Bs = sm[c & 1] + 2048;
        #pragma unroll
        for (int kb = 0; kb < 2; kb++) {
            uint32_t af[2][4], bf[4][2];
            #pragma unroll
            for (int mi = 0; mi < 2; mi++) {
                uint4 t = *(const uint4*)&As[(uint32_t)(((kb * 8 + wm * 2 + mi) * 32 + lane) * 4)];
                af[mi][0] = t.x; af[mi][1] = t.y; af[mi][2] = t.z; af[mi][3] = t.w;
            }
            #pragma unroll
            for (int ni = 0; ni < 4; ni++) {
                uint2 t = *(const uint2*)&Bs[(uint32_t)(((kb * 16 + wn * 4 + ni) * 32 + lane) * 2)];
                bf[ni][0] = t.x; bf[ni][1] = t.y;
            }
            #pragma unroll
            for (int mi = 0; mi < 2; mi++)
                #pragma unroll
                for (int ni = 0; ni < 4; ni++)
                    mma_bf16(acc[mi][ni], af[mi], bf[ni]);
        }
        if (c + 1 < NC) {
            sts((c + 1) & 1);
            __syncthreads();
        }
    }

    // ---- epilogue ----
    #pragma unroll
    for (int mi = 0; mi < 2; mi++) {
        const int r0 = bm + wm * 32 + mi * 16 + g;
        #pragma unroll
        for (int ni = 0; ni < 4; ni++) {
            const int col = bn + wn * 32 + ni * 8 + tg * 2;
            float bx = bias[col], by = bias[col + 1];
            #pragma unroll
            for (int hh = 0; hh < 2; hh++) {
                const int row = r0 + hh * 8;
                float ox = acc[mi][ni][hh * 2]     + bx;
                float oy = acc[mi][ni][hh * 2 + 1] + by;
                size_t off = (size_t)row * N + col;
                if (MODE == 1) {
                    ox = 0.5f * ox * (1.0f + erff(ox * 0.70710678118654752440f));
                    oy = 0.5f * oy * (1.0f + erff(oy * 0.70710678118654752440f));
                }
                if (MODE == 2) {
                    float2 rv = *(const float2*)(res + off);
                    ox += rv.x; oy += rv.y;
                }
                float2 o = {ox, oy};
                *(float2*)(C + off) = o;
            }
        }
    }
}

// -------- transpose: out[c*R + r] = in[r*C + c] --------
__global__ void transpose_k(const float* __restrict__ in, float* __restrict__ out,
                            int R, int Ccols) {
    __shared__ float t[32][33];
    int bx = blockIdx.x * 32, by = blockIdx.y * 32;
    int x = bx + threadIdx.x;
    #pragma unroll
    for (int i = 0; i < 32; i += 8)
        t[threadIdx.y + i][threadIdx.x] = in[(size_t)(by + threadIdx.y + i) * Ccols + x];
    __syncthreads();
    int x2 = by + threadIdx.x;
    #pragma unroll
    for (int i = 0; i < 32; i += 8)
        out[(size_t)(bx + threadIdx.y + i) * R + x2] = t[threadIdx.x][threadIdx.y + i];
}

// -------- rotation grid -> nearest-neighbor index map (input-independent) --------
__global__ void map_k() {
    int pix = blockIdx.x * blockDim.x + threadIdx.x;
    if (pix >= PIX) return;
    int h = pix >> 7;
    int w = pix & 127;
    int wi = h >> 3, p  = h & 7;
    int wj = w >> 3, q0 = w & 7;
    float seqp = -0.875f + 0.25f * (float)p;
    float seqq = -0.875f + 0.25f * (float)q0;
    float t0 = seqp / 8.0f;
    float t1 = seqq / 16.0f;
    float beta = (2.0f * ((float)wi + 0.5f) / 8.0f - 1.0f) * (PI_F * 0.5f);
    float th = t0 * (PI_F * 0.5f) + PI_F * 0.5f;
    float ph = t1 * PI_F;
    float sb = sinf(beta), cb = cosf(beta);
    float st = sinf(th),   ct = cosf(th);
    float sp = sinf(ph),   cp = cosf(ph);
    float arg = -sb * st * cp + cb * ct;
    arg = fminf(1.0f, fmaxf(-1.0f, arg));
    float new_th = acosf(arg);
    float new_ph = atan2f(st * sp, cb * st * cp + sb * ct);
    float lat = (new_th - PI_F * 0.5f) / (PI_F * 0.5f);
    lat = fminf(1.0f, fmaxf(-1.0f, lat));
    float shift = 2.0f * (0.5f - ((float)wj + 0.5f) / 16.0f);
    float lon = new_ph / PI_F - shift;
    if (lon >  1.0f) lon -= 2.0f;
    if (lon < -1.0f) lon += 2.0f;
    int iy = (int)rintf(((lat + 1.0f) * (float)Hh - 1.0f) * 0.5f);
    int ix = (int)rintf(((lon + 1.0f) * (float)Ww - 1.0f) * 0.5f);
    g_map[pix] = (iy >= 0 && iy < Hh && ix >= 0 && ix < Ww) ? (iy * Ww + ix) : -1;
}

// -------- layernorm over C=256, one block per token --------
__global__ void ln_k(const float* __restrict__ x, const float* __restrict__ g,
                     const float* __restrict__ b, float* __restrict__ out) {
    const int t = blockIdx.x, c = threadIdx.x;
    size_t base = (size_t)t * Cc;
    float v = x[base + c];
    __shared__ float red[8];
    float s = v;
    #pragma unroll
    for (int o = 16; o > 0; o >>= 1) s += __shfl_xor_sync(0xffffffffu, s, o);
    if ((c & 31) == 0) red[c >> 5] = s;
    __syncthreads();
    float mu = (((red[0]+red[1])+(red[2]+red[3]))+((red[4]+red[5])+(red[6]+red[7]))) * (1.0f/(float)Cc);
    __syncthreads();
    float d = v - mu;
    float s2 = d * d;
    #pragma unroll
    for (int o = 16; o > 0; o >>= 1) s2 += __shfl_xor_sync(0xffffffffu, s2, o);
    if ((c & 31) == 0) red[c >> 5] = s2;
    __syncthreads();
    float var = (((red[0]+red[1])+(red[2]+red[3]))+((red[4]+red[5])+(red[6]+red[7]))) * (1.0f/(float)Cc);
    out[base + c] = d * rsqrtf(var + 1e-5f) * g[c] + b[c];
}

// -------- grid-sample gather --------
__global__ void sample_k(const float* __restrict__ xn, float* __restrict__ y) {
    int pix = blockIdx.x;
    int c = threadIdx.x;
    int m = g_map[pix];
    #pragma unroll
    for (int b = 0; b < Bsz; b++) {
        float val = 0.0f;
        if (m >= 0) val = xn[((size_t)b * PIX + m) * Cc + c];
        y[((size_t)b * PIX + pix) * Cc + c] = val;
    }
}

// -------- depthwise 3x3 conv (lepe) --------
__global__ void lepe_k(const float* __restrict__ q, const float* __restrict__ rw,
                       const float* __restrict__ rb, float* __restrict__ out) {
    int gid = blockIdx.x;
    int b   = gid >> 13;
    int pix = gid & (PIX - 1);
    int h = pix >> 7, w = pix & 127;
    int c = threadIdx.x;
    float acc = rb[c];
    #pragma unroll
    for (int ky = 0; ky < 3; ky++) {
        int hh = h + ky - 1;
        if (hh < 0 || hh >= Hh) continue;
        #pragma unroll
        for (int kx = 0; kx < 3; kx++) {
            int ww = w + kx - 1;
            if (ww < 0 || ww >= Ww) continue;
            acc += q[(((size_t)b * Hh + hh) * Ww + ww) * Cc + c] * rw[c * 9 + ky * 3 + kx];
        }
    }
    out[(size_t)gid * Cc + c] = acc;
}

// -------- per-(window,head) attention --------
__global__ void __launch_bounds__(64) attn_k(
    const float* __restrict__ q, const float* __restrict__ k,
    const float* __restrict__ v, const float* __restrict__ lepe,
    float* __restrict__ out)
{
    const int blk  = blockIdx.x;
    const int head = blk & 7;
    const int win  = blk >> 3;
    const int b    = win >> 7;
    const int wrem = win & 127;
    const int wi   = wrem >> 4;
    const int wj   = wrem & 15;
    const int tid  = threadIdx.x;
    const int p    = tid >> 3;
    const int q0   = tid & 7;
    const int t    = ((b * Hh + wi * 8 + p) * Ww + wj * 8 + q0);
    const int cbase = head * 32;
    const float scale = 0.17677669529663687f;

    __shared__ float ks[64][36];
    __shared__ float vs[64][36];
    float qreg[32];
    size_t ioff = (size_t)t * Cc + cbase;
    #pragma unroll
    for (int d = 0; d < 32; d += 4) {
        float4 qq = *(const float4*)(q + ioff + d);
        qreg[d] = qq.x * scale; qreg[d+1] = qq.y * scale;
        qreg[d+2] = qq.z * scale; qreg[d+3] = qq.w * scale;
        *(float4*)&ks[tid][d] = *(const float4*)(k + ioff + d);
        *(float4*)&vs[tid][d] = *(const float4*)(v + ioff + d);
    }
    __syncthreads();

    float s[64];
    float mx = -1e30f;
    #pragma unroll
    for (int j = 0; j < 64; j++) {
        float dot = 0.0f;
        #pragma unroll
        for (int d = 0; d < 32; d += 4) {
            float4 kk = *(const float4*)&ks[j][d];
            dot += qreg[d] * kk.x + qreg[d+1] * kk.y + qreg[d+2] * kk.z + qreg[d+3] * kk.w;
        }
        s[j] = dot;
        mx = fmaxf(mx, dot);
    }
    float sum = 0.0f;
    #pragma unroll
    for (int j = 0; j < 64; j++) { float e = expf(s[j] - mx); s[j] = e; sum += e; }
    float inv = 1.0f / sum;

    float o[32];
    #pragma unroll
    for (int d = 0; d < 32; d++) o[d] = 0.0f;
    #pragma unroll
    for (int j = 0; j < 64; j++) {
        float wgt = s[j] * inv;
        #pragma unroll
        for (int d = 0; d < 32; d += 4) {
            float4 vv = *(const float4*)&vs[j][d];
            o[d] += wgt * vv.x; o[d+1] += wgt * vv.y;
            o[d+2] += wgt * vv.z; o[d+3] += wgt * vv.w;
        }
    }
    #pragma unroll
    for (int d = 0; d < 32; d += 4) {
        float4 lp = *(const float4*)(lepe + ioff + d);
        float4 r;
        r.x = o[d] + lp.x; r.y = o[d+1] + lp.y;
        r.z = o[d+2] + lp.z; r.w = o[d+3] + lp.w;
        *(float4*)(out + ioff + d) = r;
    }
}

extern "C" void kernel_launch(void* const* d_in, const int* in_sizes, int n_in,
                              void* d_out, int out_size) {
    const float* x   = (const float*)d_in[0];
    const float* n1g = (const float*)d_in[3];
    const float* n1b = (const float*)d_in[4];
    const float* wq  = (const float*)d_in[5];
    const float* bq  = (const float*)d_in[6];
    const float* wk  = (const float*)d_in[7];
    const float* bk_ = (const float*)d_in[8];
    const float* wv  = (const float*)d_in[9];
    const float* bv  = (const float*)d_in[10];
    const float* rw  = (const float*)d_in[11];
    const float* rb  = (const float*)d_in[12];
    const float* pw  = (const float*)d_in[13];
    const float* pb  = (const float*)d_in[14];
    const float* n2g = (const float*)d_in[15];
    const float* n2b = (const float*)d_in[16];
    const float* f1w = (const float*)d_in[17];
    const float* f1b = (const float*)d_in[18];
    const float* f2w = (const float*)d_in[19];
    const float* f2b = (const float*)d_in[20];
    float* out = (float*)d_out;

    float *p_xn, *p_y, *p_q, *p_k, *p_v, *p_lepe, *p_ao, *p_x2, *p_h, *p_h1, *p_bt;
    cudaGetSymbolAddress((void**)&p_xn,   g_xn);
    cudaGetSymbolAddress((void**)&p_y,    g_y);
    cudaGetSymbolAddress((void**)&p_q,    g_q);
    cudaGetSymbolAddress((void**)&p_k,    g_k);
    cudaGetSymbolAddress((void**)&p_v,    g_v);
    cudaGetSymbolAddress((void**)&p_lepe, g_lepe);
    cudaGetSymbolAddress((void**)&p_ao,   g_ao);
    cudaGetSymbolAddress((void**)&p_x2,   g_x2);
    cudaGetSymbolAddress((void**)&p_h,    g_h);
    cudaGetSymbolAddress((void**)&p_h1,   g_h1);
    cudaGetSymbolAddress((void**)&p_bt,   g_bt);

    float* wqT = p_bt;
    float* wkT = p_bt + 65536;
    float* wvT = p_bt + 2*65536;
    float* pwT = p_bt + 3*65536;
    float* f1T = p_bt + 4*65536;            // [1024][256]
    float* f2T = p_bt + 4*65536 + 262144;   // [256][1024]

    dim3 trb(32, 8);
    transpose_k<<<dim3(8, 8),  trb>>>(wq,  wqT, 256, 256);
    transpose_k<<<dim3(8, 8),  trb>>>(wk,  wkT, 256, 256);
    transpose_k<<<dim3(8, 8),  trb>>>(wv,  wvT, 256, 256);
    transpose_k<<<dim3(8, 8),  trb>>>(pw,  pwT, 256, 256);
    transpose_k<<<dim3(32, 8), trb>>>(f1w, f1T, 256, 1024);
    transpose_k<<<dim3(8, 32), trb>>>(f2w, f2T, 1024, 256);

    map_k<<<PIX / 256, 256>>>();
    ln_k<<<TOK, 256>>>(x, n1g, n1b, p_xn);
    sample_k<<<PIX, 256>>>(p_xn, p_y);

    dim3 gC(Cc / 128, TOK / 128);      // (2, 512)
    bfgemm_k<0><<<gC, 512>>>(p_xn, wqT, bq,  nullptr, p_q, Cc, Cc);
    bfgemm_k<0><<<gC, 512>>>(p_y,  wkT, bk_, nullptr, p_k, Cc, Cc);
    bfgemm_k<0><<<gC, 512>>>(p_xn, wvT, bv,  nullptr, p_v, Cc, Cc);

    lepe_k<<<TOK, 256>>>(p_q, rw, rb, p_lepe);
    attn_k<<<8192, 64>>>(p_q, p_k, p_v, p_lepe, p_ao);

    bfgemm_k<2><<<gC, 512>>>(p_ao, pwT, pb, x, p_x2, Cc, Cc);

    ln_k<<<TOK, 256>>>(p_x2, n2g, n2b, p_h);

    dim3 gF(DFF / 128, TOK / 128);     // (8, 512)
    bfgemm_k<1><<<gF, 512>>>(p_h,  f1T, f1b, nullptr, p_h1, DFF, Cc);
    bfgemm_k<2><<<gC, 512>>>(p_h1, f2T, f2b, p_x2,    out,  Cc, DFF);
}

// round 6
// speedup vs baseline: 2.4484x; 1.1253x over previous
#include <cuda_runtime.h>
#include <cuda_bf16.h>
#include <math.h>
#include <stdint.h>

// Problem constants (fixed by setup_inputs)
#define Bsz 8
#define Hh  64
#define Ww  128
#define Cc  256
#define DFF 1024
#define TOK (Bsz*Hh*Ww)   // 65536 tokens
#define PIX (Hh*Ww)       // 8192 pixels per image
#define PI_F 3.14159265358979323846f

// -------- scratch (static device globals; no runtime alloc) --------
__device__ float g_q [(size_t)TOK*Cc];
__device__ float g_k [(size_t)TOK*Cc];
__device__ float g_v [(size_t)TOK*Cc];
__device__ float g_lepe[(size_t)TOK*Cc];
__device__ float g_x2[(size_t)TOK*Cc];
__device__ __nv_bfloat16 b_xn[(size_t)TOK*Cc];
__device__ __nv_bfloat16 b_y [(size_t)TOK*Cc];
__device__ __nv_bfloat16 b_h [(size_t)TOK*Cc];
__device__ __nv_bfloat16 b_ao[(size_t)TOK*Cc];
__device__ __nv_bfloat16 b_h1[(size_t)TOK*DFF];
__device__ __nv_bfloat16 b_wt[4*65536 + 2*262144];  // wqT wkT wvT pwT f1T f2T (bf16)
__device__ int g_map[PIX];

__device__ __forceinline__ uint32_t packbf(float lo, float hi) {
    uint32_t r;
    asm("cvt.rn.bf16x2.f32 %0, %1, %2;" : "=r"(r) : "f"(hi), "f"(lo));
    return r;
}
__device__ __forceinline__ void mma_bf16(float* c, const uint32_t* a, const uint32_t* b) {
    asm volatile(
        "mma.sync.aligned.m16n8k16.row.col.f32.bf16.bf16.f32 "
        "{%0,%1,%2,%3}, {%4,%5,%6,%7}, {%8,%9}, {%0,%1,%2,%3};"
        : "+f"(c[0]), "+f"(c[1]), "+f"(c[2]), "+f"(c[3])
        : "r"(a[0]), "r"(a[1]), "r"(a[2]), "r"(a[3]), "r"(b[0]), "r"(b[1]));
}

// ======== bf16 mma.sync GEMM: C[M,N] = A[M,K] @ Bt[N,K]^T + bias (+epilogue) ========
// A, Bt are bf16 in gmem. BM=128, BN=128, BK=32; 512 threads = 16 warps (4m x 4n).
// Smem fragment-permuted bf16x2 units (validated in R4):
//   A unit: ((kb*8 + mb)*32 + lane)*4 + r      B unit: ((kb*16 + nb)*32 + lane)*2 + r
// MODE 0: +bias (f32 out)  MODE 1: gelu(+bias) (bf16 out)  MODE 2: +bias +res (f32 out)
template<int MODE>
__global__ void __launch_bounds__(512) bfgemm_k(
    const __nv_bfloat16* __restrict__ A, const __nv_bfloat16* __restrict__ Bt,
    const float* __restrict__ bias, const float* __restrict__ res,
    void* __restrict__ Cout, int N, int K)
{
    __shared__ uint32_t sm[2][4096];   // per buf: As [0,2048) | Bs [2048,4096)
    const int tid = threadIdx.x;
    const int wid = tid >> 5, lane = tid & 31;
    const int g = lane >> 2, tg = lane & 3;
    const int wm = wid >> 2, wn = wid & 3;     // warp grid 4x4
    const int bm = blockIdx.y * 128;
    const int bn = blockIdx.x * 128;
    const int NC = K >> 5;

    const int row = tid >> 2, kq = tid & 3;    // gmem slot: row 0..127, 8-elem quad 0..3
    const int kb = kq >> 1, i2 = kq & 1;
    // A store base: mb/ga/i1
    const int mb = row >> 4, gr = row & 15, ga = gr & 7, i1 = gr >> 3;
    const uint32_t abase = (uint32_t)(((kb * 8 + mb) * 32 + ga * 4) * 4 + i1 + 2 * i2);
    // B store base: nb/gb
    const int nb = row >> 3, gb = row & 7;
    const uint32_t bbase = (uint32_t)(((kb * 16 + nb) * 32 + gb * 4) * 2 + i2);

    float acc[2][4][4];
    #pragma unroll
    for (int mi = 0; mi < 2; mi++)
        #pragma unroll
        for (int ni = 0; ni < 4; ni++)
            #pragma unroll
            for (int r = 0; r < 4; r++) acc[mi][ni][r] = 0.0f;

    uint4 au, bu;
    auto ldg = [&](int c) {
        const int k0 = c << 5;
        au = *(const uint4*)(A  + (size_t)(bm + row) * K + k0 + kq * 8);
        bu = *(const uint4*)(Bt + (size_t)(bn + row) * K + k0 + kq * 8);
    };
    auto sts = [&](int buf) {
        uint32_t* As = sm[buf];
        uint32_t* Bs = sm[buf] + 2048;
        As[abase]      = au.x; As[abase + 4]  = au.y;
        As[abase + 8]  = au.z; As[abase + 12] = au.w;
        Bs[bbase]      = bu.x; Bs[bbase + 2]  = bu.y;
        Bs[bbase + 4]  = bu.z; Bs[bbase + 6]  = bu.w;
    };

    ldg(0);
    sts(0);
    __syncthreads();

    for (int c = 0; c < NC; c++) {
        if (c + 1 < NC) ldg(c + 1);
        const uint32_t* As = sm[c & 1];
        const uint32_t* Bs = sm[c & 1] + 2048;
        #pragma unroll
        for (int kk = 0; kk < 2; kk++) {
            uint32_t af[2][4], bf[4][2];
            #pragma unroll
            for (int mi = 0; mi < 2; mi++) {
                uint4 t = *(const uint4*)&As[(uint32_t)(((kk * 8 + wm * 2 + mi) * 32 + lane) * 4)];
                af[mi][0] = t.x; af[mi][1] = t.y; af[mi][2] = t.z; af[mi][3] = t.w;
            }
            #pragma unroll
            for (int ni = 0; ni < 4; ni++) {
                uint2 t = *(const uint2*)&Bs[(uint32_t)(((kk * 16 + wn * 4 + ni) * 32 + lane) * 2)];
                bf[ni][0] = t.x; bf[ni][1] = t.y;
            }
            #pragma unroll
            for (int mi = 0; mi < 2; mi++)
                #pragma unroll
                for (int ni = 0; ni < 4; ni++)
                    mma_bf16(acc[mi][ni], af[mi], bf[ni]);
        }
        if (c + 1 < NC) {
            sts((c + 1) & 1);
            __syncthreads();
        }
    }

    // ---- epilogue ----
    #pragma unroll
    for (int mi = 0; mi < 2; mi++) {
        const int r0 = bm + wm * 32 + mi * 16 + g;
        #pragma unroll
        for (int ni = 0; ni < 4; ni++) {
            const int col = bn + wn * 32 + ni * 8 + tg * 2;
            float bx = bias[col], by = bias[col + 1];
            #pragma unroll
            for (int hh = 0; hh < 2; hh++) {
                const int rr = r0 + hh * 8;
                float ox = acc[mi][ni][hh * 2]     + bx;
                float oy = acc[mi][ni][hh * 2 + 1] + by;
                size_t off = (size_t)rr * N + col;
                if (MODE == 1) {
                    ox = 0.5f * ox * (1.0f + erff(ox * 0.70710678118654752440f));
                    oy = 0.5f * oy * (1.0f + erff(oy * 0.70710678118654752440f));
                    ((uint32_t*)Cout)[off >> 1] = packbf(ox, oy);
                } else {
                    if (MODE == 2) {
                        float2 rv = *(const float2*)(res + off);
                        ox += rv.x; oy += rv.y;
                    }
                    float2 o = {ox, oy};
                    *(float2*)((float*)Cout + off) = o;
                }
            }
        }
    }
}

// -------- transpose + cvt: out[c*R + r] = bf16(in[r*C + c]) --------
__global__ void transpose_k(const float* __restrict__ in, __nv_bfloat16* __restrict__ out,
                            int R, int Ccols) {
    __shared__ float t[32][33];
    int bx = blockIdx.x * 32, by = blockIdx.y * 32;
    int x = bx + threadIdx.x;
    #pragma unroll
    for (int i = 0; i < 32; i += 8)
        t[threadIdx.y + i][threadIdx.x] = in[(size_t)(by + threadIdx.y + i) * Ccols + x];
    __syncthreads();
    int x2 = by + threadIdx.x;
    #pragma unroll
    for (int i = 0; i < 32; i += 8)
        out[(size_t)(bx + threadIdx.y + i) * R + x2] = __float2bfloat16(t[threadIdx.x][threadIdx.y + i]);
}

// -------- rotation grid -> nearest-neighbor index map --------
__global__ void map_k() {
    int pix = blockIdx.x * blockDim.x + threadIdx.x;
    if (pix >= PIX) return;
    int h = pix >> 7;
    int w = pix & 127;
    int wi = h >> 3, p  = h & 7;
    int wj = w >> 3, q0 = w & 7;
    float seqp = -0.875f + 0.25f * (float)p;
    float seqq = -0.875f + 0.25f * (float)q0;
    float t0 = seqp / 8.0f;
    float t1 = seqq / 16.0f;
    float beta = (2.0f * ((float)wi + 0.5f) / 8.0f - 1.0f) * (PI_F * 0.5f);
    float th = t0 * (PI_F * 0.5f) + PI_F * 0.5f;
    float ph = t1 * PI_F;
    float sb = sinf(beta), cb = cosf(beta);
    float st = sinf(th),   ct = cosf(th);
    float sp = sinf(ph),   cp = cosf(ph);
    float arg = -sb * st * cp + cb * ct;
    arg = fminf(1.0f, fmaxf(-1.0f, arg));
    float new_th = acosf(arg);
    float new_ph = atan2f(st * sp, cb * st * cp + sb * ct);
    float lat = (new_th - PI_F * 0.5f) / (PI_F * 0.5f);
    lat = fminf(1.0f, fmaxf(-1.0f, lat));
    float shift = 2.0f * (0.5f - ((float)wj + 0.5f) / 16.0f);
    float lon = new_ph / PI_F - shift;
    if (lon >  1.0f) lon -= 2.0f;
    if (lon < -1.0f) lon += 2.0f;
    int iy = (int)rintf(((lat + 1.0f) * (float)Hh - 1.0f) * 0.5f);
    int ix = (int)rintf(((lon + 1.0f) * (float)Ww - 1.0f) * 0.5f);
    g_map[pix] = (iy >= 0 && iy < Hh && ix >= 0 && ix < Ww) ? (iy * Ww + ix) : -1;
}

// -------- layernorm over C=256, bf16 output --------
__global__ void ln_k(const float* __restrict__ x, const float* __restrict__ g,
                     const float* __restrict__ b, __nv_bfloat16* __restrict__ out) {
    const int t = blockIdx.x, c = threadIdx.x;
    size_t base = (size_t)t * Cc;
    float v = x[base + c];
    __shared__ float red[8];
    float s = v;
    #pragma unroll
    for (int o = 16; o > 0; o >>= 1) s += __shfl_xor_sync(0xffffffffu, s, o);
    if ((c & 31) == 0) red[c >> 5] = s;
    __syncthreads();
    float mu = (((red[0]+red[1])+(red[2]+red[3]))+((red[4]+red[5])+(red[6]+red[7]))) * (1.0f/(float)Cc);
    __syncthreads();
    float d = v - mu;
    float s2 = d * d;
    #pragma unroll
    for (int o = 16; o > 0; o >>= 1) s2 += __shfl_xor_sync(0xffffffffu, s2, o);
    if ((c & 31) == 0) red[c >> 5] = s2;
    __syncthreads();
    float var = (((red[0]+red[1])+(red[2]+red[3]))+((red[4]+red[5])+(red[6]+red[7]))) * (1.0f/(float)Cc);
    out[base + c] = __float2bfloat16(d * rsqrtf(var + 1e-5f) * g[c] + b[c]);
}

// -------- grid-sample gather (bf16) --------
__global__ void sample_k(const __nv_bfloat16* __restrict__ xn, __nv_bfloat16* __restrict__ y) {
    int pix = blockIdx.x;
    int c = threadIdx.x;
    int m = g_map[pix];
    #pragma unroll
    for (int b = 0; b < Bsz; b++) {
        __nv_bfloat16 val = __float2bfloat16(0.0f);
        if (m >= 0) val = xn[((size_t)b * PIX + m) * Cc + c];
        y[((size_t)b * PIX + pix) * Cc + c] = val;
    }
}

// -------- depthwise 3x3 conv (lepe), fp32 --------
__global__ void lepe_k(const float* __restrict__ q, const float* __restrict__ rw,
                       const float* __restrict__ rb, float* __restrict__ out) {
    int gid = blockIdx.x;
    int b   = gid >> 13;
    int pix = gid & (PIX - 1);
    int h = pix >> 7, w = pix & 127;
    int c = threadIdx.x;
    float acc = rb[c];
    #pragma unroll
    for (int ky = 0; ky < 3; ky++) {
        int hh = h + ky - 1;
        if (hh < 0 || hh >= Hh) continue;
        #pragma unroll
        for (int kx = 0; kx < 3; kx++) {
            int ww = w + kx - 1;
            if (ww < 0 || ww >= Ww) continue;
            acc += q[(((size_t)b * Hh + hh) * Ww + ww) * Cc + c] * rw[c * 9 + ky * 3 + kx];
        }
    }
    out[(size_t)gid * Cc + c] = acc;
}

// -------- per-(window,head) attention; bf16 output (ao) --------
__global__ void __launch_bounds__(64) attn_k(
    const float* __restrict__ q, const float* __restrict__ k,
    const float* __restrict__ v, const float* __restrict__ lepe,
    __nv_bfloat16* __restrict__ out)
{
    const int blk  = blockIdx.x;
    const int head = blk & 7;
    const int win  = blk >> 3;
    const int b    = win >> 7;
    const int wrem = win & 127;
    const int wi   = wrem >> 4;
    const int wj   = wrem & 15;
    const int tid  = threadIdx.x;
    const int p    = tid >> 3;
    const int q0   = tid & 7;
    const int t    = ((b * Hh + wi * 8 + p) * Ww + wj * 8 + q0);
    const int cbase = head * 32;
    const float scale = 0.17677669529663687f;

    __shared__ float ks[64][36];
    __shared__ float vs[64][36];
    float qreg[32];
    size_t ioff = (size_t)t * Cc + cbase;
    #pragma unroll
    for (int d = 0; d < 32; d += 4) {
        float4 qq = *(const float4*)(q + ioff + d);
        qreg[d] = qq.x * scale; qreg[d+1] = qq.y * scale;
        qreg[d+2] = qq.z * scale; qreg[d+3] = qq.w * scale;
        *(float4*)&ks[tid][d] = *(const float4*)(k + ioff + d);
        *(float4*)&vs[tid][d] = *(const float4*)(v + ioff + d);
    }
    __syncthreads();

    float s[64];
    float mx = -1e30f;
    #pragma unroll
    for (int j = 0; j < 64; j++) {
        float dot = 0.0f;
        #pragma unroll
        for (int d = 0; d < 32; d += 4) {
            float4 kk = *(const float4*)&ks[j][d];
            dot += qreg[d] * kk.x + qreg[d+1] * kk.y + qreg[d+2] * kk.z + qreg[d+3] * kk.w;
        }
        s[j] = dot;
        mx = fmaxf(mx, dot);
    }
    float sum = 0.0f;
    #pragma unroll
    for (int j = 0; j < 64; j++) { float e = expf(s[j] - mx); s[j] = e; sum += e; }
    float inv = 1.0f / sum;

    float o[32];
    #pragma unroll
    for (int d = 0; d < 32; d++) o[d] = 0.0f;
    #pragma unroll
    for (int j = 0; j < 64; j++) {
        float wgt = s[j] * inv;
        #pragma unroll
        for (int d = 0; d < 32; d += 4) {
            float4 vv = *(const float4*)&vs[j][d];
            o[d] += wgt * vv.x; o[d+1] += wgt * vv.y;
            o[d+2] += wgt * vv.z; o[d+3] += wgt * vv.w;
        }
    }
    uint32_t* ob = (uint32_t*)(out + ioff);
    #pragma unroll
    for (int d = 0; d < 32; d += 4) {
        float4 lp = *(const float4*)(lepe + ioff + d);
        ob[(d >> 1)]     = packbf(o[d]   + lp.x, o[d+1] + lp.y);
        ob[(d >> 1) + 1] = packbf(o[d+2] + lp.z, o[d+3] + lp.w);
    }
}

extern "C" void kernel_launch(void* const* d_in, const int* in_sizes, int n_in,
                              void* d_out, int out_size) {
    const float* x   = (const float*)d_in[0];
    const float* n1g = (const float*)d_in[3];
    const float* n1b = (const float*)d_in[4];
    const float* wq  = (const float*)d_in[5];
    const float* bq  = (const float*)d_in[6];
    const float* wk  = (const float*)d_in[7];
    const float* bk_ = (const float*)d_in[8];
    const float* wv  = (const float*)d_in[9];
    const float* bv  = (const float*)d_in[10];
    const float* rw  = (const float*)d_in[11];
    const float* rb  = (const float*)d_in[12];
    const float* pw  = (const float*)d_in[13];
    const float* pb  = (const float*)d_in[14];
    const float* n2g = (const float*)d_in[15];
    const float* n2b = (const float*)d_in[16];
    const float* f1w = (const float*)d_in[17];
    const float* f1b = (const float*)d_in[18];
    const float* f2w = (const float*)d_in[19];
    const float* f2b = (const float*)d_in[20];
    float* out = (float*)d_out;

    float *p_q, *p_k, *p_v, *p_lepe, *p_x2;
    __nv_bfloat16 *p_xn, *p_y, *p_h, *p_ao, *p_h1, *p_wt;
    cudaGetSymbolAddress((void**)&p_q,    g_q);
    cudaGetSymbolAddress((void**)&p_k,    g_k);
    cudaGetSymbolAddress((void**)&p_v,    g_v);
    cudaGetSymbolAddress((void**)&p_lepe, g_lepe);
    cudaGetSymbolAddress((void**)&p_x2,   g_x2);
    cudaGetSymbolAddress((void**)&p_xn,   b_xn);
    cudaGetSymbolAddress((void**)&p_y,    b_y);
    cudaGetSymbolAddress((void**)&p_h,    b_h);
    cudaGetSymbolAddress((void**)&p_ao,   b_ao);
    cudaGetSymbolAddress((void**)&p_h1,   b_h1);
    cudaGetSymbolAddress((void**)&p_wt,   b_wt);

    __nv_bfloat16* wqT = p_wt;
    __nv_bfloat16* wkT = p_wt + 65536;
    __nv_bfloat16* wvT = p_wt + 2*65536;
    __nv_bfloat16* pwT = p_wt + 3*65536;
    __nv_bfloat16* f1T = p_wt + 4*65536;            // [1024][256]
    __nv_bfloat16* f2T = p_wt + 4*65536 + 262144;   // [256][1024]

    dim3 trb(32, 8);
    transpose_k<<<dim3(8, 8),  trb>>>(wq,  wqT, 256, 256);
    transpose_k<<<dim3(8, 8),  trb>>>(wk,  wkT, 256, 256);
    transpose_k<<<dim3(8, 8),  trb>>>(wv,  wvT, 256, 256);
    transpose_k<<<dim3(8, 8),  trb>>>(pw,  pwT, 256, 256);
    transpose_k<<<dim3(32, 8), trb>>>(f1w, f1T, 256, 1024);
    transpose_k<<<dim3(8, 32), trb>>>(f2w, f2T, 1024, 256);

    map_k<<<PIX / 256, 256>>>();
    ln_k<<<TOK, 256>>>(x, n1g, n1b, p_xn);
    sample_k<<<PIX, 256>>>(p_xn, p_y);

    dim3 gC(Cc / 128, TOK / 128);      // (2, 512)
    bfgemm_k<0><<<gC, 512>>>(p_xn, wqT, bq,  nullptr, p_q, Cc, Cc);
    bfgemm_k<0><<<gC, 512>>>(p_y,  wkT, bk_, nullptr, p_k, Cc, Cc);
    bfgemm_k<0><<<gC, 512>>>(p_xn, wvT, bv,  nullptr, p_v, Cc, Cc);

    lepe_k<<<TOK, 256>>>(p_q, rw, rb, p_lepe);
    attn_k<<<8192, 64>>>(p_q, p_k, p_v, p_lepe, p_ao);

    bfgemm_k<2><<<gC, 512>>>(p_ao, pwT, pb, x, p_x2, Cc, Cc);

    ln_k<<<TOK, 256>>>(p_x2, n2g, n2b, p_h);

    dim3 gF(DFF / 128, TOK / 128);     // (8, 512)
    bfgemm_k<1><<<gF, 512>>>(p_h,  f1T, f1b, nullptr, p_h1, DFF, Cc);
    bfgemm_k<2><<<gC, 512>>>(p_h1, f2T, f2b, p_x2,    out,  Cc, DFF);
}

// round 7
// speedup vs baseline: 2.4761x; 1.0113x over previous
#include <cuda_runtime.h>
#include <cuda_bf16.h>
#include <math.h>
#include <stdint.h>

// Problem constants (fixed by setup_inputs)
#define Bsz 8
#define Hh  64
#define Ww  128
#define Cc  256
#define DFF 1024
#define TOK (Bsz*Hh*Ww)   // 65536 tokens
#define PIX (Hh*Ww)       // 8192 pixels per image
#define PI_F 3.14159265358979323846f

// -------- scratch (static device globals; no runtime alloc) --------
__device__ float g_x2[(size_t)TOK*Cc];
__device__ __nv_bfloat16 b_xn[(size_t)TOK*Cc];
__device__ __nv_bfloat16 b_q [(size_t)TOK*Cc];
__device__ __nv_bfloat16 b_k [(size_t)TOK*Cc];
__device__ __nv_bfloat16 b_v [(size_t)TOK*Cc];
__device__ __nv_bfloat16 b_lepe[(size_t)TOK*Cc];
__device__ __nv_bfloat16 b_h [(size_t)TOK*Cc];
__device__ __nv_bfloat16 b_ao[(size_t)TOK*Cc];
__device__ __nv_bfloat16 b_h1[(size_t)TOK*DFF];
__device__ __nv_bfloat16 b_wt[4*65536 + 2*262144];  // wqT wkT wvT pwT f1T f2T (bf16)
__device__ int g_map[PIX];

__device__ __forceinline__ uint32_t packbf(float lo, float hi) {
    uint32_t r;
    asm("cvt.rn.bf16x2.f32 %0, %1, %2;" : "=r"(r) : "f"(hi), "f"(lo));
    return r;
}
__device__ __forceinline__ void mma_bf16(float* c, const uint32_t* a, const uint32_t* b) {
    asm volatile(
        "mma.sync.aligned.m16n8k16.row.col.f32.bf16.bf16.f32 "
        "{%0,%1,%2,%3}, {%4,%5,%6,%7}, {%8,%9}, {%0,%1,%2,%3};"
        : "+f"(c[0]), "+f"(c[1]), "+f"(c[2]), "+f"(c[3])
        : "r"(a[0]), "r"(a[1]), "r"(a[2]), "r"(a[3]), "r"(b[0]), "r"(b[1]));
}

// ======== bf16 mma.sync GEMM: C[M,N] = A[M,K] @ Bt[N,K]^T + bias (+epilogue) ========
// BM=128, BN=128, BK=64; 512 threads = 16 warps (4m x 4n); warp tile 32x32.
// Double-buffered 64KB dynamic smem; fragment-permuted bf16x2 units (validated R4-R6):
//   A unit: ((kb*8 + mb)*32 + lane)*4 + r      B unit: ((kb*16 + nb)*32 + lane)*2 + r
// MODE 1: gelu(+bias) bf16 out   MODE 2: +bias +res f32 out   MODE 3: +bias bf16 out
// GATHER: A row r is xn row map[r] (zero if invalid) — fuses grid-sample into K-GEMM.
template<int MODE, int GATHER>
__global__ void __launch_bounds__(512) bfgemm_k(
    const __nv_bfloat16* __restrict__ A, const __nv_bfloat16* __restrict__ Bt,
    const float* __restrict__ bias, const float* __restrict__ res,
    void* __restrict__ Cout, int N, int K)
{
    extern __shared__ uint32_t sm[];   // [2][8192]: per buf A 4096 | B 4096 units
    const int tid = threadIdx.x;
    const int wid = tid >> 5, lane = tid & 31;
    const int g = lane >> 2, tg = lane & 3;
    const int wm = wid >> 2, wn = wid & 3;     // warp grid 4x4
    const int bm = blockIdx.y * 128;
    const int bn = blockIdx.x * 128;
    const int NC = K >> 6;

    // per-slot (2 slots/thread) staging geometry
    uint32_t abase[2], bbase[2];
    const __nv_bfloat16* Ap[2];
    const __nv_bfloat16* Bp[2];
    bool aval[2];
    #pragma unroll
    for (int i = 0; i < 2; i++) {
        int s = tid + i * 512;
        int row = s >> 3, kq = s & 7;
        int kb = kq >> 1, i2 = kq & 1;
        int mb = row >> 4, gr = row & 15, ga = gr & 7, i1 = gr >> 3;
        abase[i] = (uint32_t)(((kb * 8 + mb) * 32 + ga * 4) * 4 + i1 + 2 * i2);
        int nb = row >> 3, gb = row & 7;
        bbase[i] = (uint32_t)(((kb * 16 + nb) * 32 + gb * 4) * 2 + i2);
        int grow = bm + row;
        if (GATHER) {
            int b = grow >> 13, pix = grow & (PIX - 1);
            int m = g_map[pix];
            aval[i] = (m >= 0);
            Ap[i] = A + (size_t)(b * PIX + (m >= 0 ? m : 0)) * K + kq * 8;
        } else {
            aval[i] = true;
            Ap[i] = A + (size_t)grow * K + kq * 8;
        }
        Bp[i] = Bt + (size_t)(bn + row) * K + kq * 8;
    }

    float acc[2][4][4];
    #pragma unroll
    for (int mi = 0; mi < 2; mi++)
        #pragma unroll
        for (int ni = 0; ni < 4; ni++)
            #pragma unroll
            for (int r = 0; r < 4; r++) acc[mi][ni][r] = 0.0f;

    uint4 au[2], bu[2];
    auto ldg = [&](int c) {
        const int k0 = c << 6;
        #pragma unroll
        for (int i = 0; i < 2; i++) {
            au[i] = aval[i] ? *(const uint4*)(Ap[i] + k0) : make_uint4(0, 0, 0, 0);
            bu[i] = *(const uint4*)(Bp[i] + k0);
        }
    };
    auto sts = [&](int buf) {
        uint32_t* As = sm + buf * 8192;
        uint32_t* Bs = As + 4096;
        #pragma unroll
        for (int i = 0; i < 2; i++) {
            As[abase[i]]      = au[i].x; As[abase[i] + 4]  = au[i].y;
            As[abase[i] + 8]  = au[i].z; As[abase[i] + 12] = au[i].w;
            Bs[bbase[i]]      = bu[i].x; Bs[bbase[i] + 2]  = bu[i].y;
            Bs[bbase[i] + 4]  = bu[i].z; Bs[bbase[i] + 6]  = bu[i].w;
        }
    };

    ldg(0);
    sts(0);
    __syncthreads();

    for (int c = 0; c < NC; c++) {
        if (c + 1 < NC) ldg(c + 1);
        const uint32_t* As = sm + (c & 1) * 8192;
        const uint32_t* Bs = As + 4096;
        #pragma unroll
        for (int kk = 0; kk < 4; kk++) {
            uint32_t af[2][4], bf[4][2];
            #pragma unroll
            for (int mi = 0; mi < 2; mi++) {
                uint4 t = *(const uint4*)&As[(uint32_t)(((kk * 8 + wm * 2 + mi) * 32 + lane) * 4)];
                af[mi][0] = t.x; af[mi][1] = t.y; af[mi][2] = t.z; af[mi][3] = t.w;
            }
            #pragma unroll
            for (int ni = 0; ni < 4; ni++) {
                uint2 t = *(const uint2*)&Bs[(uint32_t)(((kk * 16 + wn * 4 + ni) * 32 + lane) * 2)];
                bf[ni][0] = t.x; bf[ni][1] = t.y;
            }
            #pragma unroll
            for (int mi = 0; mi < 2; mi++)
                #pragma unroll
                for (int ni = 0; ni < 4; ni++)
                    mma_bf16(acc[mi][ni], af[mi], bf[ni]);
        }
        if (c + 1 < NC) {
            sts((c + 1) & 1);
            __syncthreads();
        }
    }

    // ---- epilogue ----
    #pragma unroll
    for (int mi = 0; mi < 2; mi++) {
        const int r0 = bm + wm * 32 + mi * 16 + g;
        #pragma unroll
        for (int ni = 0; ni < 4; ni++) {
            const int col = bn + wn * 32 + ni * 8 + tg * 2;
            float bx = bias[col], by = bias[col + 1];
            #pragma unroll
            for (int hh = 0; hh < 2; hh++) {
                const int rr = r0 + hh * 8;
                float ox = acc[mi][ni][hh * 2]     + bx;
                float oy = acc[mi][ni][hh * 2 + 1] + by;
                size_t off = (size_t)rr * N + col;
                if (MODE == 1) {
                    ox = 0.5f * ox * (1.0f + erff(ox * 0.70710678118654752440f));
                    oy = 0.5f * oy * (1.0f + erff(oy * 0.70710678118654752440f));
                    ((uint32_t*)Cout)[off >> 1] = packbf(ox, oy);
                } else if (MODE == 3) {
                    ((uint32_t*)Cout)[off >> 1] = packbf(ox, oy);
                } else {
                    float2 rv = *(const float2*)(res + off);
                    ox += rv.x; oy += rv.y;
                    float2 o = {ox, oy};
                    *(float2*)((float*)Cout + off) = o;
                }
            }
        }
    }
}

// -------- 4x fused transpose + cvt (256x256 weights) --------
__global__ void transpose4_k(const float* __restrict__ i0, const float* __restrict__ i1,
                             const float* __restrict__ i2, const float* __restrict__ i3,
                             __nv_bfloat16* __restrict__ o0, __nv_bfloat16* __restrict__ o1,
                             __nv_bfloat16* __restrict__ o2, __nv_bfloat16* __restrict__ o3) {
    const float* in  = (blockIdx.z == 0) ? i0 : (blockIdx.z == 1) ? i1 : (blockIdx.z == 2) ? i2 : i3;
    __nv_bfloat16* out = (blockIdx.z == 0) ? o0 : (blockIdx.z == 1) ? o1 : (blockIdx.z == 2) ? o2 : o3;
    __shared__ float t[32][33];
    int bx = blockIdx.x * 32, by = blockIdx.y * 32;
    int x = bx + threadIdx.x;
    #pragma unroll
    for (int i = 0; i < 32; i += 8)
        t[threadIdx.y + i][threadIdx.x] = in[(size_t)(by + threadIdx.y + i) * 256 + x];
    __syncthreads();
    int x2 = by + threadIdx.x;
    #pragma unroll
    for (int i = 0; i < 32; i += 8)
        out[(size_t)(bx + threadIdx.y + i) * 256 + x2] = __float2bfloat16(t[threadIdx.x][threadIdx.y + i]);
}

// -------- transpose + cvt: out[c*R + r] = bf16(in[r*C + c]) --------
__global__ void transpose_k(const float* __restrict__ in, __nv_bfloat16* __restrict__ out,
                            int R, int Ccols) {
    __shared__ float t[32][33];
    int bx = blockIdx.x * 32, by = blockIdx.y * 32;
    int x = bx + threadIdx.x;
    #pragma unroll
    for (int i = 0; i < 32; i += 8)
        t[threadIdx.y + i][threadIdx.x] = in[(size_t)(by + threadIdx.y + i) * Ccols + x];
    __syncthreads();
    int x2 = by + threadIdx.x;
    #pragma unroll
    for (int i = 0; i < 32; i += 8)
        out[(size_t)(bx + threadIdx.y + i) * R + x2] = __float2bfloat16(t[threadIdx.x][threadIdx.y + i]);
}

// -------- rotation grid -> nearest-neighbor index map --------
__global__ void map_k() {
    int pix = blockIdx.x * blockDim.x + threadIdx.x;
    if (pix >= PIX) return;
    int h = pix >> 7;
    int w = pix & 127;
    int wi = h >> 3, p  = h & 7;
    int wj = w >> 3, q0 = w & 7;
    float seqp = -0.875f + 0.25f * (float)p;
    float seqq = -0.875f + 0.25f * (float)q0;
    float t0 = seqp / 8.0f;
    float t1 = seqq / 16.0f;
    float beta = (2.0f * ((float)wi + 0.5f) / 8.0f - 1.0f) * (PI_F * 0.5f);
    float th = t0 * (PI_F * 0.5f) + PI_F * 0.5f;
    float ph = t1 * PI_F;
    float sb = sinf(beta), cb = cosf(beta);
    float st = sinf(th),   ct = cosf(th);
    float sp = sinf(ph),   cp = cosf(ph);
    float arg = -sb * st * cp + cb * ct;
    arg = fminf(1.0f, fmaxf(-1.0f, arg));
    float new_th = acosf(arg);
    float new_ph = atan2f(st * sp, cb * st * cp + sb * ct);
    float lat = (new_th - PI_F * 0.5f) / (PI_F * 0.5f);
    lat = fminf(1.0f, fmaxf(-1.0f, lat));
    float shift = 2.0f * (0.5f - ((float)wj + 0.5f) / 16.0f);
    float lon = new_ph / PI_F - shift;
    if (lon >  1.0f) lon -= 2.0f;
    if (lon < -1.0f) lon += 2.0f;
    int iy = (int)rintf(((lat + 1.0f) * (float)Hh - 1.0f) * 0.5f);
    int ix = (int)rintf(((lon + 1.0f) * (float)Ww - 1.0f) * 0.5f);
    g_map[pix] = (iy >= 0 && iy < Hh && ix >= 0 && ix < Ww) ? (iy * Ww + ix) : -1;
}

// -------- layernorm over C=256, bf16 output --------
__global__ void ln_k(const float* __restrict__ x, const float* __restrict__ g,
                     const float* __restrict__ b, __nv_bfloat16* __restrict__ out) {
    const int t = blockIdx.x, c = threadIdx.x;
    size_t base = (size_t)t * Cc;
    float v = x[base + c];
    __shared__ float red[8];
    float s = v;
    #pragma unroll
    for (int o = 16; o > 0; o >>= 1) s += __shfl_xor_sync(0xffffffffu, s, o);
    if ((c & 31) == 0) red[c >> 5] = s;
    __syncthreads();
    float mu = (((red[0]+red[1])+(red[2]+red[3]))+((red[4]+red[5])+(red[6]+red[7]))) * (1.0f/(float)Cc);
    __syncthreads();
    float d = v - mu;
    float s2 = d * d;
    #pragma unroll
    for (int o = 16; o > 0; o >>= 1) s2 += __shfl_xor_sync(0xffffffffu, s2, o);
    if ((c & 31) == 0) red[c >> 5] = s2;
    __syncthreads();
    float var = (((red[0]+red[1])+(red[2]+red[3]))+((red[4]+red[5])+(red[6]+red[7]))) * (1.0f/(float)Cc);
    out[base + c] = __float2bfloat16(d * rsqrtf(var + 1e-5f) * g[c] + b[c]);
}

// -------- depthwise 3x3 conv (lepe), bf16 in/out --------
__global__ void lepe_k(const __nv_bfloat16* __restrict__ q, const float* __restrict__ rw,
                       const float* __restrict__ rb, __nv_bfloat16* __restrict__ out) {
    int gid = blockIdx.x;
    int b   = gid >> 13;
    int pix = gid & (PIX - 1);
    int h = pix >> 7, w = pix & 127;
    int c = threadIdx.x;
    float acc = rb[c];
    #pragma unroll
    for (int ky = 0; ky < 3; ky++) {
        int hh = h + ky - 1;
        if (hh < 0 || hh >= Hh) continue;
        #pragma unroll
        for (int kx = 0; kx < 3; kx++) {
            int ww = w + kx - 1;
            if (ww < 0 || ww >= Ww) continue;
            acc += __bfloat162float(q[(((size_t)b * Hh + hh) * Ww + ww) * Cc + c]) * rw[c * 9 + ky * 3 + kx];
        }
    }
    out[(size_t)gid * Cc + c] = __float2bfloat16(acc);
}

// -------- per-(window,head) attention; bf16 in/out --------
__global__ void __launch_bounds__(64) attn_k(
    const __nv_bfloat16* __restrict__ q, const __nv_bfloat16* __restrict__ k,
    const __nv_bfloat16* __restrict__ v, const __nv_bfloat16* __restrict__ lepe,
    __nv_bfloat16* __restrict__ out)
{
    const int blk  = blockIdx.x;
    const int head = blk & 7;
    const int win  = blk >> 3;
    const int b    = win >> 7;
    const int wrem = win & 127;
    const int wi   = wrem >> 4;
    const int wj   = wrem & 15;
    const int tid  = threadIdx.x;
    const int p    = tid >> 3;
    const int q0   = tid & 7;
    const int t    = ((b * Hh + wi * 8 + p) * Ww + wj * 8 + q0);
    const int cbase = head * 32;
    const float scale = 0.17677669529663687f;

    __shared__ float ks[64][36];
    __shared__ float vs[64][36];
    float qreg[32];
    size_t ioff = (size_t)t * Cc + cbase;
    #pragma unroll
    for (int d = 0; d < 32; d += 8) {
        uint4 qq = *(const uint4*)(q + ioff + d);
        uint4 kk = *(const uint4*)(k + ioff + d);
        uint4 vv = *(const uint4*)(v + ioff + d);
        const uint32_t* qp = (const uint32_t*)&qq;
        const uint32_t* kp = (const uint32_t*)&kk;
        const uint32_t* vp = (const uint32_t*)&vv;
        #pragma unroll
        for (int e = 0; e < 4; e++) {
            float2 qf = __bfloat1622float2(*(const __nv_bfloat162*)&qp[e]);
            float2 kf = __bfloat1622float2(*(const __nv_bfloat162*)&kp[e]);
            float2 vf = __bfloat1622float2(*(const __nv_bfloat162*)&vp[e]);
            qreg[d + e*2]     = qf.x * scale;
            qreg[d + e*2 + 1] = qf.y * scale;
            ks[tid][d + e*2] = kf.x; ks[tid][d + e*2 + 1] = kf.y;
            vs[tid][d + e*2] = vf.x; vs[tid][d + e*2 + 1] = vf.y;
        }
    }
    __syncthreads();

    float s[64];
    float mx = -1e30f;
    #pragma unroll
    for (int j = 0; j < 64; j++) {
        float dot = 0.0f;
        #pragma unroll
        for (int d = 0; d < 32; d += 4) {
            float4 kk = *(const float4*)&ks[j][d];
            dot += qreg[d] * kk.x + qreg[d+1] * kk.y + qreg[d+2] * kk.z + qreg[d+3] * kk.w;
        }
        s[j] = dot;
        mx = fmaxf(mx, dot);
    }
    float sum = 0.0f;
    #pragma unroll
    for (int j = 0; j < 64; j++) { float e = expf(s[j] - mx); s[j] = e; sum += e; }
    float inv = 1.0f / sum;

    float o[32];
    #pragma unroll
    for (int d = 0; d < 32; d++) o[d] = 0.0f;
    #pragma unroll
    for (int j = 0; j < 64; j++) {
        float wgt = s[j] * inv;
        #pragma unroll
        for (int d = 0; d < 32; d += 4) {
            float4 vv = *(const float4*)&vs[j][d];
            o[d] += wgt * vv.x; o[d+1] += wgt * vv.y;
            o[d+2] += wgt * vv.z; o[d+3] += wgt * vv.w;
        }
    }
    uint32_t* ob = (uint32_t*)(out + ioff);
    #pragma unroll
    for (int d = 0; d < 32; d += 4) {
        uint2 lpu = *(const uint2*)(lepe + ioff + d);
        float2 l0 = __bfloat1622float2(*(const __nv_bfloat162*)&lpu.x);
        float2 l1 = __bfloat1622float2(*(const __nv_bfloat162*)&lpu.y);
        ob[(d >> 1)]     = packbf(o[d]   + l0.x, o[d+1] + l0.y);
        ob[(d >> 1) + 1] = packbf(o[d+2] + l1.x, o[d+3] + l1.y);
    }
}

extern "C" void kernel_launch(void* const* d_in, const int* in_sizes, int n_in,
                              void* d_out, int out_size) {
    const float* x   = (const float*)d_in[0];
    const float* n1g = (const float*)d_in[3];
    const float* n1b = (const float*)d_in[4];
    const float* wq  = (const float*)d_in[5];
    const float* bq  = (const float*)d_in[6];
    const float* wk  = (const float*)d_in[7];
    const float* bk_ = (const float*)d_in[8];
    const float* wv  = (const float*)d_in[9];
    const float* bv  = (const float*)d_in[10];
    const float* rw  = (const float*)d_in[11];
    const float* rb  = (const float*)d_in[12];
    const float* pw  = (const float*)d_in[13];
    const float* pb  = (const float*)d_in[14];
    const float* n2g = (const float*)d_in[15];
    const float* n2b = (const float*)d_in[16];
    const float* f1w = (const float*)d_in[17];
    const float* f1b = (const float*)d_in[18];
    const float* f2w = (const float*)d_in[19];
    const float* f2b = (const float*)d_in[20];
    float* out = (float*)d_out;

    float* p_x2;
    __nv_bfloat16 *p_xn, *p_q, *p_k, *p_v, *p_lepe, *p_h, *p_ao, *p_h1, *p_wt;
    cudaGetSymbolAddress((void**)&p_x2,   g_x2);
    cudaGetSymbolAddress((void**)&p_xn,   b_xn);
    cudaGetSymbolAddress((void**)&p_q,    b_q);
    cudaGetSymbolAddress((void**)&p_k,    b_k);
    cudaGetSymbolAddress((void**)&p_v,    b_v);
    cudaGetSymbolAddress((void**)&p_lepe, b_lepe);
    cudaGetSymbolAddress((void**)&p_h,    b_h);
    cudaGetSymbolAddress((void**)&p_ao,   b_ao);
    cudaGetSymbolAddress((void**)&p_h1,   b_h1);
    cudaGetSymbolAddress((void**)&p_wt,   b_wt);

    __nv_bfloat16* wqT = p_wt;
    __nv_bfloat16* wkT = p_wt + 65536;
    __nv_bfloat16* wvT = p_wt + 2*65536;
    __nv_bfloat16* pwT = p_wt + 3*65536;
    __nv_bfloat16* f1T = p_wt + 4*65536;            // [1024][256]
    __nv_bfloat16* f2T = p_wt + 4*65536 + 262144;   // [256][1024]

    const int SMB = 65536;
    cudaFuncSetAttribute(bfgemm_k<1,0>, cudaFuncAttributeMaxDynamicSharedMemorySize, SMB);
    cudaFuncSetAttribute(bfgemm_k<2,0>, cudaFuncAttributeMaxDynamicSharedMemorySize, SMB);
    cudaFuncSetAttribute(bfgemm_k<3,0>, cudaFuncAttributeMaxDynamicSharedMemorySize, SMB);
    cudaFuncSetAttribute(bfgemm_k<3,1>, cudaFuncAttributeMaxDynamicSharedMemorySize, SMB);

    transpose4_k<<<dim3(8, 8, 4), dim3(32, 8)>>>(wq, wk, wv, pw, wqT, wkT, wvT, pwT);
    transpose_k<<<dim3(32, 8), dim3(32, 8)>>>(f1w, f1T, 256, 1024);
    transpose_k<<<dim3(8, 32), dim3(32, 8)>>>(f2w, f2T, 1024, 256);

    map_k<<<PIX / 256, 256>>>();
    ln_k<<<TOK, 256>>>(x, n1g, n1b, p_xn);

    dim3 gC(Cc / 128, TOK / 128);      // (2, 512)
    bfgemm_k<3,0><<<gC, 512, SMB>>>(p_xn, wqT, bq,  nullptr, p_q, Cc, Cc);
    bfgemm_k<3,1><<<gC, 512, SMB>>>(p_xn, wkT, bk_, nullptr, p_k, Cc, Cc);
    bfgemm_k<3,0><<<gC, 512, SMB>>>(p_xn, wvT, bv,  nullptr, p_v, Cc, Cc);

    lepe_k<<<TOK, 256>>>(p_q, rw, rb, p_lepe);
    attn_k<<<8192, 64>>>(p_q, p_k, p_v, p_lepe, p_ao);

    bfgemm_k<2,0><<<gC, 512, SMB>>>(p_ao, pwT, pb, x, p_x2, Cc, Cc);

    ln_k<<<TOK, 256>>>(p_x2, n2g, n2b, p_h);

    dim3 gF(DFF / 128, TOK / 128);     // (8, 512)
    bfgemm_k<1,0><<<gF, 512, SMB>>>(p_h,  f1T, f1b, nullptr, p_h1, DFF, Cc);
    bfgemm_k<2,0><<<gC, 512, SMB>>>(p_h1, f2T, f2b, p_x2,    out,  Cc, DFF);
}